// round 1
// baseline (speedup 1.0000x reference)
#include <cuda_runtime.h>

#define Bb 8
#define Nn 4096
#define Cc 128
#define Kk 20

// ------------------------- scratch (device globals, no allocs) -------------
__device__ float4 g_pts4[Bb*Nn];          // x,y,z,norm2
__device__ int    g_knn[Bb*Nn*Kk];        // 20 neighbor indices per point (global b*N+n space)
__device__ float  g_wT[2*Cc*Cc];          // WcT then WgT, [c][o]
__device__ float  g_center[Bb*Cc*Nn];     // Wc @ leaky(p)         [b][o][n]
__device__ float  g_gT[Bb*Nn*Cc];         // (Wg @ leaky(p))^T     [b][n][o]

// ------------------------- prep: pack xyz + transpose weights --------------
__global__ __launch_bounds__(256) void prep_kernel(const float* __restrict__ xyz,
                                                   const float* __restrict__ Wc,
                                                   const float* __restrict__ Wg) {
    int id = blockIdx.x * 256 + threadIdx.x;
    if (id < Bb*Nn) {
        int b = id >> 12;
        int n = id & (Nn - 1);
        const float* p = xyz + b * 3 * Nn;
        float x = p[n], y = p[Nn + n], z = p[2*Nn + n];
        g_pts4[id] = make_float4(x, y, z, fmaf(x, x, fmaf(y, y, z * z)));
    } else {
        int t = id - Bb*Nn;                 // 0 .. 2*128*128-1
        int which = t >> 14;                // 0: Wc, 1: Wg
        int e = t & (Cc*Cc - 1);
        int o = e >> 7, c = e & 127;
        const float* W = which ? Wg : Wc;
        g_wT[which*Cc*Cc + c*Cc + o] = W[o*Cc + c];
    }
}

// ------------------------- KNN -------------------------------------------
#define KNN_TILE 1024
#define KNN_BUF  16

__device__ __forceinline__ void knn_flush(float (&ds)[20], int (&ix)[20],
                                          const float (&bd)[KNN_BUF],
                                          const int   (&bi)[KNN_BUF], int cnt) {
    #pragma unroll
    for (int u = 0; u < KNN_BUF; ++u) {
        if (u < cnt) {
            float cd = bd[u];
            int   ci = bi[u];
            if (cd < ds[19]) {
                #pragma unroll
                for (int s = 0; s < 20; ++s) {
                    bool take = cd < ds[s];        // strict: stable ties (earlier index wins)
                    float td = ds[s]; int ti = ix[s];
                    if (take) { ds[s] = cd; ix[s] = ci; cd = td; ci = ti; }
                }
            }
        }
    }
}

__global__ __launch_bounds__(128) void knn_kernel() {
    __shared__ float4 tile[KNN_TILE];
    int gi   = blockIdx.x * 128 + threadIdx.x;   // global point id b*N+n
    int base = gi & ~(Nn - 1);                   // batch base
    float4 me = g_pts4[gi];
    float mx = -2.f * me.x, my = -2.f * me.y, mz = -2.f * me.z;

    const float INF = 3.402823466e38f;
    float ds[20]; int ix[20];
    #pragma unroll
    for (int s = 0; s < 20; ++s) { ds[s] = INF; ix[s] = 0; }
    float bd[KNN_BUF]; int bi[KNN_BUF];
    int cnt = 0;
    float worst = INF;

    for (int t0 = 0; t0 < Nn; t0 += KNN_TILE) {
        __syncthreads();
        #pragma unroll
        for (int u = 0; u < KNN_TILE/128; ++u)
            tile[threadIdx.x + u*128] = g_pts4[base + t0 + threadIdx.x + u*128];
        __syncthreads();

        #pragma unroll 8
        for (int jj = 0; jj < KNN_TILE; ++jj) {
            float4 c = tile[jj];
            // rank key: n_j - 2*dot(x_i, x_j)  (ordering == squared distance ordering)
            float d = fmaf(mx, c.x, fmaf(my, c.y, fmaf(mz, c.z, c.w)));
            int j = base + t0 + jj;
            if (d < worst && j != gi) { bd[cnt] = d; bi[cnt] = j; ++cnt; }
            if (__any_sync(0xffffffffu, cnt >= KNN_BUF)) {
                knn_flush(ds, ix, bd, bi, cnt);
                worst = ds[19];
                cnt = 0;
            }
        }
    }
    knn_flush(ds, ix, bd, bi, cnt);
    #pragma unroll
    for (int s = 0; s < 20; ++s) g_knn[gi*20 + s] = ix[s];
}

// ------------------------- fused GEMM: [Wc;Wg] @ leaky(P) ------------------
// grid (N/128, B, 2); z=0 -> center [b][o][n], z=1 -> gT transposed [b][n][o]
__global__ __launch_bounds__(256) void gemm_kernel(const float* __restrict__ points) {
    __shared__ __align__(16) float Ws[32][128];   // [c][o]
    __shared__ __align__(16) float Ps[32][128];   // [c][n]
    int b  = blockIdx.y;
    int n0 = blockIdx.x * 128;
    int which = blockIdx.z;
    const float* WT = g_wT + which * Cc * Cc;
    const float* P  = points + b * Cc * Nn;
    int tid = threadIdx.x;
    int tx = tid & 15, ty = tid >> 4;

    unsigned long long acc[8][4];                 // 8 rows x 4 fp32x2 col-pairs
    #pragma unroll
    for (int r = 0; r < 8; ++r)
        #pragma unroll
        for (int q = 0; q < 4; ++q) acc[r][q] = 0ull;

    for (int kc = 0; kc < Cc; kc += 32) {
        __syncthreads();
        #pragma unroll
        for (int i = 0; i < 4; ++i) {
            int f4 = tid + i * 256;               // 0..1023 float4 slots
            int c = f4 >> 5, n4 = f4 & 31;
            *(float4*)&Ws[c][n4*4] = *(const float4*)(WT + (kc + c)*Cc + n4*4);
            float4 pv = *(const float4*)(P + (kc + c)*Nn + n0 + n4*4);
            pv.x = fmaxf(pv.x, 0.f) + 0.01f * fminf(pv.x, 0.f);
            pv.y = fmaxf(pv.y, 0.f) + 0.01f * fminf(pv.y, 0.f);
            pv.z = fmaxf(pv.z, 0.f) + 0.01f * fminf(pv.z, 0.f);
            pv.w = fmaxf(pv.w, 0.f) + 0.01f * fminf(pv.w, 0.f);
            *(float4*)&Ps[c][n4*4] = pv;
        }
        __syncthreads();
        #pragma unroll
        for (int c = 0; c < 32; ++c) {
            float a[8];
            *(float4*)&a[0] = *(float4*)&Ws[c][ty*8];
            *(float4*)&a[4] = *(float4*)&Ws[c][ty*8 + 4];
            unsigned long long bp[4];
            *(ulonglong2*)&bp[0] = *(ulonglong2*)&Ps[c][tx*8];
            *(ulonglong2*)&bp[2] = *(ulonglong2*)&Ps[c][tx*8 + 4];
            #pragma unroll
            for (int r = 0; r < 8; ++r) {
                unsigned long long av;
                asm("mov.b64 %0, {%1, %1};" : "=l"(av) : "f"(a[r]));
                #pragma unroll
                for (int q = 0; q < 4; ++q)
                    asm("fma.rn.f32x2 %0, %1, %2, %0;"
                        : "+l"(acc[r][q]) : "l"(av), "l"(bp[q]));
            }
        }
    }

    union U { unsigned long long u; float2 f; };
    if (which == 0) {
        #pragma unroll
        for (int r = 0; r < 8; ++r) {
            int o = ty*8 + r;
            float v[8];
            #pragma unroll
            for (int q = 0; q < 4; ++q) { U t; t.u = acc[r][q]; v[2*q] = t.f.x; v[2*q+1] = t.f.y; }
            float* dst = g_center + (b*Cc + o)*Nn + n0 + tx*8;
            *(float4*)dst       = make_float4(v[0], v[1], v[2], v[3]);
            *(float4*)(dst + 4) = make_float4(v[4], v[5], v[6], v[7]);
        }
    } else {
        #pragma unroll
        for (int q = 0; q < 4; ++q) {
            float lo[8], hi[8];
            #pragma unroll
            for (int r = 0; r < 8; ++r) { U t; t.u = acc[r][q]; lo[r] = t.f.x; hi[r] = t.f.y; }
            int n = n0 + tx*8 + 2*q;
            float* d0 = g_gT + (b*Nn + n    )*Cc + ty*8;
            float* d1 = g_gT + (b*Nn + n + 1)*Cc + ty*8;
            *(float4*)d0       = make_float4(lo[0], lo[1], lo[2], lo[3]);
            *(float4*)(d0 + 4) = make_float4(lo[4], lo[5], lo[6], lo[7]);
            *(float4*)d1       = make_float4(hi[0], hi[1], hi[2], hi[3]);
            *(float4*)(d1 + 4) = make_float4(hi[4], hi[5], hi[6], hi[7]);
        }
    }
}

// ------------------------- combine: gather-sum + center + bias + residual --
__global__ __launch_bounds__(256) void combine_kernel(const float* __restrict__ points,
                                                      const float* __restrict__ bc,
                                                      const float* __restrict__ bg,
                                                      float* __restrict__ out) {
    __shared__ float sm[32][133];     // [n_local][o], pad 133 -> conflict-free transpose
    __shared__ int   sidx[32*20];
    int b  = blockIdx.y;
    int n0 = blockIdx.x * 32;
    int tid = threadIdx.x;

    for (int u = tid; u < 32*20; u += 256)
        sidx[u] = g_knn[(b*Nn + n0)*20 + u];
    __syncthreads();

    // phase A: neighbor gather-sum into sm[nl][o]
    int h = tid >> 7, o = tid & 127;
    for (int nl = h; nl < 32; nl += 2) {
        float acc = 0.f;
        #pragma unroll
        for (int k = 0; k < Kk; ++k) {
            int nb = sidx[nl*20 + k];          // global b*N+n index
            acc += g_gT[nb*Cc + o];
        }
        sm[nl][o] = acc;
    }
    __syncthreads();

    // phase B: transposed, coalesced write with center + bias + shortcut
    int w = tid >> 5, l = tid & 31;
    int n = n0 + l;
    #pragma unroll
    for (int oo = 0; oo < 16; ++oo) {
        int o2 = w + oo*8;
        int off = (b*Cc + o2)*Nn + n;
        float biasv = fmaf(20.f, bg[o2], bc[o2]);
        out[off] = (sm[l][o2] + g_center[off] + biasv) * (1.0f / 21.0f) + points[off];
    }
}

// ------------------------- launch -----------------------------------------
extern "C" void kernel_launch(void* const* d_in, const int* in_sizes, int n_in,
                              void* d_out, int out_size) {
    const float* xyz    = (const float*)d_in[0];
    const float* points = (const float*)d_in[1];
    const float* Wc     = (const float*)d_in[2];
    const float* bc     = (const float*)d_in[3];
    const float* Wg     = (const float*)d_in[4];
    const float* bg     = (const float*)d_in[5];
    float* out = (float*)d_out;

    prep_kernel<<<256, 256>>>(xyz, Wc, Wg);
    knn_kernel<<<Bb*Nn/128, 128>>>();
    gemm_kernel<<<dim3(Nn/128, Bb, 2), 256>>>(points);
    combine_kernel<<<dim3(Nn/32, Bb), 256>>>(points, bc, bg, out);
}

// round 2
// speedup vs baseline: 1.6685x; 1.6685x over previous
#include <cuda_runtime.h>

#define Bb 8
#define Nn 4096
#define Cc 128
#define Kk 20

// ------------------------- scratch (device globals, no allocs) -------------
__device__ float4 g_pts4[Bb*Nn];          // x,y,z,norm2
__device__ int    g_knn[Bb*Nn*Kk];        // 20 neighbor indices per point (global b*N+n space)
__device__ float  g_wT[2*Cc*Cc];          // WcT then WgT, [c][o]
__device__ float  g_center[Bb*Cc*Nn];     // Wc @ leaky(p)         [b][o][n]
__device__ float  g_gT[Bb*Nn*Cc];         // (Wg @ leaky(p))^T     [b][n][o]

// ------------------------- prep: pack xyz + transpose weights --------------
__global__ __launch_bounds__(256) void prep_kernel(const float* __restrict__ xyz,
                                                   const float* __restrict__ Wc,
                                                   const float* __restrict__ Wg) {
    int id = blockIdx.x * 256 + threadIdx.x;
    if (id < Bb*Nn) {
        int b = id >> 12;
        int n = id & (Nn - 1);
        const float* p = xyz + b * 3 * Nn;
        float x = p[n], y = p[Nn + n], z = p[2*Nn + n];
        g_pts4[id] = make_float4(x, y, z, fmaf(x, x, fmaf(y, y, z * z)));
    } else {
        int t = id - Bb*Nn;                 // 0 .. 2*128*128-1
        int which = t >> 14;                // 0: Wc, 1: Wg
        int e = t & (Cc*Cc - 1);
        int o = e >> 7, c = e & 127;
        const float* W = which ? Wg : Wc;
        g_wT[which*Cc*Cc + c*Cc + o] = W[o*Cc + c];
    }
}

// ------------------------- KNN -------------------------------------------
// Per thread: one query point. Sorted top-20 (ds ascending) lives entirely in
// registers (all indices static). Qualifying candidates go into a 2-deep
// STATIC shift buffer (register moves only); a warp vote drains the buffers
// into the sorted list only when some lane has 2 pending, amortizing the
// 20-stage insertion across ~64 candidates warp-wide.
#define KNN_TILE 1024

__device__ __forceinline__ void knn_insert(float (&ds)[20], int (&ix)[20],
                                           float cd, int ci, bool valid) {
    if (valid && cd < ds[19]) {
        #pragma unroll
        for (int s = 0; s < 20; ++s) {
            bool take = cd < ds[s];          // strict: earlier index wins ties
            float td = ds[s]; int ti = ix[s];
            if (take) { ds[s] = cd; ix[s] = ci; cd = td; ci = ti; }
        }
    }
}

__global__ __launch_bounds__(128) void knn_kernel() {
    __shared__ float4 tile[KNN_TILE];
    int gi   = blockIdx.x * 128 + threadIdx.x;   // global point id b*N+n
    int base = gi & ~(Nn - 1);                   // batch base
    float4 me = g_pts4[gi];
    float mx = -2.f * me.x, my = -2.f * me.y, mz = -2.f * me.z;

    const float INF = 3.402823466e38f;
    float ds[20]; int ix[20];
    #pragma unroll
    for (int s = 0; s < 20; ++s) { ds[s] = INF; ix[s] = 0; }

    float b0d = 0.f, b1d = 0.f;                  // static 2-deep shift buffer
    int   b0i = 0,   b1i = 0;
    int   cnt = 0;
    float worst = INF;

    for (int t0 = 0; t0 < Nn; t0 += KNN_TILE) {
        __syncthreads();
        #pragma unroll
        for (int u = 0; u < KNN_TILE/128; ++u)
            tile[threadIdx.x + u*128] = g_pts4[base + t0 + threadIdx.x + u*128];
        __syncthreads();

        #pragma unroll 8
        for (int jj = 0; jj < KNN_TILE; ++jj) {
            float4 c = tile[jj];
            // rank key: n_j - 2*dot(x_i, x_j)  (same ordering as squared dist)
            float d = fmaf(mx, c.x, fmaf(my, c.y, fmaf(mz, c.z, c.w)));
            int j = base + t0 + jj;
            bool q = (d < worst) & (j != gi);
            if (q) { b1d = b0d; b1i = b0i; b0d = d; b0i = j; ++cnt; }
            if (__any_sync(0xffffffffu, cnt >= 2)) {
                knn_insert(ds, ix, b1d, b1i, cnt > 1);   // oldest first (tie stability)
                knn_insert(ds, ix, b0d, b0i, cnt > 0);
                worst = ds[19];
                cnt = 0;
            }
        }
    }
    knn_insert(ds, ix, b1d, b1i, cnt > 1);
    knn_insert(ds, ix, b0d, b0i, cnt > 0);

    #pragma unroll
    for (int s = 0; s < 20; ++s) g_knn[gi*20 + s] = ix[s];
}

// ------------------------- fused GEMM: [Wc;Wg] @ leaky(P) ------------------
// grid (N/128, B, 2); z=0 -> center [b][o][n], z=1 -> gT transposed [b][n][o]
__global__ __launch_bounds__(256) void gemm_kernel(const float* __restrict__ points) {
    __shared__ __align__(16) float Ws[32][128];   // [c][o]
    __shared__ __align__(16) float Ps[32][128];   // [c][n]
    int b  = blockIdx.y;
    int n0 = blockIdx.x * 128;
    int which = blockIdx.z;
    const float* WT = g_wT + which * Cc * Cc;
    const float* P  = points + b * Cc * Nn;
    int tid = threadIdx.x;
    int tx = tid & 15, ty = tid >> 4;

    unsigned long long acc[8][4];                 // 8 rows x 4 fp32x2 col-pairs
    #pragma unroll
    for (int r = 0; r < 8; ++r)
        #pragma unroll
        for (int q = 0; q < 4; ++q) acc[r][q] = 0ull;

    for (int kc = 0; kc < Cc; kc += 32) {
        __syncthreads();
        #pragma unroll
        for (int i = 0; i < 4; ++i) {
            int f4 = tid + i * 256;               // 0..1023 float4 slots
            int c = f4 >> 5, n4 = f4 & 31;
            *(float4*)&Ws[c][n4*4] = *(const float4*)(WT + (kc + c)*Cc + n4*4);
            float4 pv = *(const float4*)(P + (kc + c)*Nn + n0 + n4*4);
            pv.x = fmaxf(pv.x, 0.f) + 0.01f * fminf(pv.x, 0.f);
            pv.y = fmaxf(pv.y, 0.f) + 0.01f * fminf(pv.y, 0.f);
            pv.z = fmaxf(pv.z, 0.f) + 0.01f * fminf(pv.z, 0.f);
            pv.w = fmaxf(pv.w, 0.f) + 0.01f * fminf(pv.w, 0.f);
            *(float4*)&Ps[c][n4*4] = pv;
        }
        __syncthreads();
        #pragma unroll
        for (int c = 0; c < 32; ++c) {
            float a[8];
            *(float4*)&a[0] = *(float4*)&Ws[c][ty*8];
            *(float4*)&a[4] = *(float4*)&Ws[c][ty*8 + 4];
            unsigned long long bp[4];
            *(ulonglong2*)&bp[0] = *(ulonglong2*)&Ps[c][tx*8];
            *(ulonglong2*)&bp[2] = *(ulonglong2*)&Ps[c][tx*8 + 4];
            #pragma unroll
            for (int r = 0; r < 8; ++r) {
                unsigned long long av;
                asm("mov.b64 %0, {%1, %1};" : "=l"(av) : "f"(a[r]));
                #pragma unroll
                for (int q = 0; q < 4; ++q)
                    asm("fma.rn.f32x2 %0, %1, %2, %0;"
                        : "+l"(acc[r][q]) : "l"(av), "l"(bp[q]));
            }
        }
    }

    union U { unsigned long long u; float2 f; };
    if (which == 0) {
        #pragma unroll
        for (int r = 0; r < 8; ++r) {
            int o = ty*8 + r;
            float v[8];
            #pragma unroll
            for (int q = 0; q < 4; ++q) { U t; t.u = acc[r][q]; v[2*q] = t.f.x; v[2*q+1] = t.f.y; }
            float* dst = g_center + (b*Cc + o)*Nn + n0 + tx*8;
            *(float4*)dst       = make_float4(v[0], v[1], v[2], v[3]);
            *(float4*)(dst + 4) = make_float4(v[4], v[5], v[6], v[7]);
        }
    } else {
        #pragma unroll
        for (int q = 0; q < 4; ++q) {
            float lo[8], hi[8];
            #pragma unroll
            for (int r = 0; r < 8; ++r) { U t; t.u = acc[r][q]; lo[r] = t.f.x; hi[r] = t.f.y; }
            int n = n0 + tx*8 + 2*q;
            float* d0 = g_gT + (b*Nn + n    )*Cc + ty*8;
            float* d1 = g_gT + (b*Nn + n + 1)*Cc + ty*8;
            *(float4*)d0       = make_float4(lo[0], lo[1], lo[2], lo[3]);
            *(float4*)(d0 + 4) = make_float4(lo[4], lo[5], lo[6], lo[7]);
            *(float4*)d1       = make_float4(hi[0], hi[1], hi[2], hi[3]);
            *(float4*)(d1 + 4) = make_float4(hi[4], hi[5], hi[6], hi[7]);
        }
    }
}

// ------------------------- combine: gather-sum + center + bias + residual --
__global__ __launch_bounds__(256) void combine_kernel(const float* __restrict__ points,
                                                      const float* __restrict__ bc,
                                                      const float* __restrict__ bg,
                                                      float* __restrict__ out) {
    __shared__ float sm[32][133];     // [n_local][o], pad 133 -> conflict-free transpose
    __shared__ int   sidx[32*20];
    int b  = blockIdx.y;
    int n0 = blockIdx.x * 32;
    int tid = threadIdx.x;

    for (int u = tid; u < 32*20; u += 256)
        sidx[u] = g_knn[(b*Nn + n0)*20 + u];
    __syncthreads();

    // phase A: neighbor gather-sum into sm[nl][o]
    int h = tid >> 7, o = tid & 127;
    for (int nl = h; nl < 32; nl += 2) {
        float acc = 0.f;
        #pragma unroll
        for (int k = 0; k < Kk; ++k) {
            int nb = sidx[nl*20 + k];          // global b*N+n index
            acc += g_gT[nb*Cc + o];
        }
        sm[nl][o] = acc;
    }
    __syncthreads();

    // phase B: transposed, coalesced write with center + bias + shortcut
    int w = tid >> 5, l = tid & 31;
    int n = n0 + l;
    #pragma unroll
    for (int oo = 0; oo < 16; ++oo) {
        int o2 = w + oo*8;
        int off = (b*Cc + o2)*Nn + n;
        float biasv = fmaf(20.f, bg[o2], bc[o2]);
        out[off] = (sm[l][o2] + g_center[off] + biasv) * (1.0f / 21.0f) + points[off];
    }
}

// ------------------------- launch -----------------------------------------
extern "C" void kernel_launch(void* const* d_in, const int* in_sizes, int n_in,
                              void* d_out, int out_size) {
    const float* xyz    = (const float*)d_in[0];
    const float* points = (const float*)d_in[1];
    const float* Wc     = (const float*)d_in[2];
    const float* bc     = (const float*)d_in[3];
    const float* Wg     = (const float*)d_in[4];
    const float* bg     = (const float*)d_in[5];
    float* out = (float*)d_out;

    prep_kernel<<<256, 256>>>(xyz, Wc, Wg);
    knn_kernel<<<Bb*Nn/128, 128>>>();
    gemm_kernel<<<dim3(Nn/128, Bb, 2), 256>>>(points);
    combine_kernel<<<dim3(Nn/32, Bb), 256>>>(points, bc, bg, out);
}

// round 3
// speedup vs baseline: 1.9061x; 1.1424x over previous
#include <cuda_runtime.h>

#define Bb 8
#define Nn 4096
#define Cc 128
#define Kk 20

// ------------------------- scratch (device globals, no allocs) -------------
__device__ float4 g_pts4[Bb*Nn];          // x,y,z,norm2
__device__ int    g_knn[Bb*Nn*Kk];        // 20 neighbor indices per point (global b*N+n space)
__device__ float  g_wT[2*Cc*Cc];          // WcT then WgT, [c][o]
__device__ float  g_center[Bb*Cc*Nn];     // Wc @ leaky(p)         [b][o][n]
__device__ float  g_gT[Bb*Nn*Cc];         // (Wg @ leaky(p))^T     [b][n][o]

// ------------------------- prep: pack xyz + transpose weights --------------
__global__ __launch_bounds__(256) void prep_kernel(const float* __restrict__ xyz,
                                                   const float* __restrict__ Wc,
                                                   const float* __restrict__ Wg) {
    int id = blockIdx.x * 256 + threadIdx.x;
    if (id < Bb*Nn) {
        int b = id >> 12;
        int n = id & (Nn - 1);
        const float* p = xyz + b * 3 * Nn;
        float x = p[n], y = p[Nn + n], z = p[2*Nn + n];
        g_pts4[id] = make_float4(x, y, z, fmaf(x, x, fmaf(y, y, z * z)));
    } else {
        int t = id - Bb*Nn;                 // 0 .. 2*128*128-1
        int which = t >> 14;                // 0: Wc, 1: Wg
        int e = t & (Cc*Cc - 1);
        int o = e >> 7, c = e & 127;
        const float* W = which ? Wg : Wc;
        g_wT[which*Cc*Cc + c*Cc + o] = W[o*Cc + c];
    }
}

// ------------------------- KNN -------------------------------------------
// One query per thread. Top-21 (self included: self's rank key -|x|^2 is the
// strict minimum, so slot 0 is always self and we emit slots 1..20).
// Sorted list maintained with an FMNMX compare-swap network: value chain is
// fmin/fmax (lat 4, no predicates); index chain is FSETP->SEL (pred-as-data,
// lat 4). A static 2-deep sentinel buffer + warp vote amortizes insert
// executions across the warp; invalid slots flush as +INF (no-op through the
// min/max network), keeping the flush branch-free inside.
#define KNN_TILE 1024
#define KNN_INF  3.402823466e38f
#define KNN_SENT (-3.0e38f)

__device__ __forceinline__ void knn_ins(float (&ds)[21], int (&ix)[21],
                                        float cd, int ci) {
    #pragma unroll
    for (int s = 0; s < 21; ++s) {
        bool t   = cd < ds[s];               // strict: earlier insert wins ties
        float mn = fminf(cd, ds[s]);
        float mx = fmaxf(cd, ds[s]);
        int  ni  = t ? ci : ix[s];
        ci       = t ? ix[s] : ci;
        ds[s] = mn; ix[s] = ni; cd = mx;
    }
}

__global__ __launch_bounds__(128) void knn_kernel() {
    __shared__ float4 tile[KNN_TILE];
    int gi   = blockIdx.x * 128 + threadIdx.x;   // global point id b*N+n
    int base = gi & ~(Nn - 1);                   // batch base (block is batch-uniform)
    float4 me = g_pts4[gi];
    float mx = -2.f * me.x, my = -2.f * me.y, mz = -2.f * me.z;

    float ds[21]; int ix[21];
    #pragma unroll
    for (int s = 0; s < 21; ++s) { ds[s] = KNN_INF; ix[s] = 0; }

    float b0d = KNN_SENT, b1d = KNN_SENT;        // static 2-deep shift buffer
    int   b0i = 0,         b1i = 0;
    float worst = KNN_INF;                       // ds[20]

    for (int t0 = 0; t0 < Nn; t0 += KNN_TILE) {
        __syncthreads();
        #pragma unroll
        for (int u = 0; u < KNN_TILE/128; ++u)
            tile[threadIdx.x + u*128] = g_pts4[base + t0 + threadIdx.x + u*128];
        __syncthreads();

        int jbase = base + t0;
        #pragma unroll 1
        for (int jj = 0; jj < KNN_TILE; ++jj) {
            float4 c = tile[jj];
            // rank key: n_j - 2*dot(x_i, x_j)  (same ordering as squared dist)
            float d = fmaf(mx, c.x, fmaf(my, c.y, fmaf(mz, c.z, c.w)));
            int j = jbase + jj;
            bool q = d < worst;                  // self qualifies exactly once
            if (q) { b1d = b0d; b1i = b0i; b0d = d; b0i = j; }
            if (__any_sync(0xffffffffu, b1d != KNN_SENT)) {
                float c1 = (b1d != KNN_SENT) ? b1d : KNN_INF;   // oldest first
                float c0 = (b0d != KNN_SENT) ? b0d : KNN_INF;
                knn_ins(ds, ix, c1, b1i);
                knn_ins(ds, ix, c0, b0i);
                worst = ds[20];
                b0d = KNN_SENT; b1d = KNN_SENT;
            }
        }
    }
    {   // final drain (vote guarantees at most b0 pending, drain both anyway)
        float c1 = (b1d != KNN_SENT) ? b1d : KNN_INF;
        float c0 = (b0d != KNN_SENT) ? b0d : KNN_INF;
        knn_ins(ds, ix, c1, b1i);
        knn_ins(ds, ix, c0, b0i);
    }

    #pragma unroll
    for (int s = 0; s < 20; ++s) g_knn[gi*20 + s] = ix[s + 1];   // drop self
}

// ------------------------- fused GEMM: [Wc;Wg] @ leaky(P) ------------------
// grid (N/128, B, 2); z=0 -> center [b][o][n], z=1 -> gT transposed [b][n][o]
__global__ __launch_bounds__(256) void gemm_kernel(const float* __restrict__ points) {
    __shared__ __align__(16) float Ws[32][128];   // [c][o]
    __shared__ __align__(16) float Ps[32][128];   // [c][n]
    int b  = blockIdx.y;
    int n0 = blockIdx.x * 128;
    int which = blockIdx.z;
    const float* WT = g_wT + which * Cc * Cc;
    const float* P  = points + b * Cc * Nn;
    int tid = threadIdx.x;
    int tx = tid & 15, ty = tid >> 4;

    unsigned long long acc[8][4];                 // 8 rows x 4 fp32x2 col-pairs
    #pragma unroll
    for (int r = 0; r < 8; ++r)
        #pragma unroll
        for (int q = 0; q < 4; ++q) acc[r][q] = 0ull;

    for (int kc = 0; kc < Cc; kc += 32) {
        __syncthreads();
        #pragma unroll
        for (int i = 0; i < 4; ++i) {
            int f4 = tid + i * 256;               // 0..1023 float4 slots
            int c = f4 >> 5, n4 = f4 & 31;
            *(float4*)&Ws[c][n4*4] = *(const float4*)(WT + (kc + c)*Cc + n4*4);
            float4 pv = *(const float4*)(P + (kc + c)*Nn + n0 + n4*4);
            pv.x = fmaxf(pv.x, 0.f) + 0.01f * fminf(pv.x, 0.f);
            pv.y = fmaxf(pv.y, 0.f) + 0.01f * fminf(pv.y, 0.f);
            pv.z = fmaxf(pv.z, 0.f) + 0.01f * fminf(pv.z, 0.f);
            pv.w = fmaxf(pv.w, 0.f) + 0.01f * fminf(pv.w, 0.f);
            *(float4*)&Ps[c][n4*4] = pv;
        }
        __syncthreads();
        #pragma unroll
        for (int c = 0; c < 32; ++c) {
            float a[8];
            *(float4*)&a[0] = *(float4*)&Ws[c][ty*8];
            *(float4*)&a[4] = *(float4*)&Ws[c][ty*8 + 4];
            unsigned long long bp[4];
            *(ulonglong2*)&bp[0] = *(ulonglong2*)&Ps[c][tx*8];
            *(ulonglong2*)&bp[2] = *(ulonglong2*)&Ps[c][tx*8 + 4];
            #pragma unroll
            for (int r = 0; r < 8; ++r) {
                unsigned long long av;
                asm("mov.b64 %0, {%1, %1};" : "=l"(av) : "f"(a[r]));
                #pragma unroll
                for (int q = 0; q < 4; ++q)
                    asm("fma.rn.f32x2 %0, %1, %2, %0;"
                        : "+l"(acc[r][q]) : "l"(av), "l"(bp[q]));
            }
        }
    }

    union U { unsigned long long u; float2 f; };
    if (which == 0) {
        #pragma unroll
        for (int r = 0; r < 8; ++r) {
            int o = ty*8 + r;
            float v[8];
            #pragma unroll
            for (int q = 0; q < 4; ++q) { U t; t.u = acc[r][q]; v[2*q] = t.f.x; v[2*q+1] = t.f.y; }
            float* dst = g_center + (b*Cc + o)*Nn + n0 + tx*8;
            *(float4*)dst       = make_float4(v[0], v[1], v[2], v[3]);
            *(float4*)(dst + 4) = make_float4(v[4], v[5], v[6], v[7]);
        }
    } else {
        #pragma unroll
        for (int q = 0; q < 4; ++q) {
            float lo[8], hi[8];
            #pragma unroll
            for (int r = 0; r < 8; ++r) { U t; t.u = acc[r][q]; lo[r] = t.f.x; hi[r] = t.f.y; }
            int n = n0 + tx*8 + 2*q;
            float* d0 = g_gT + (b*Nn + n    )*Cc + ty*8;
            float* d1 = g_gT + (b*Nn + n + 1)*Cc + ty*8;
            *(float4*)d0       = make_float4(lo[0], lo[1], lo[2], lo[3]);
            *(float4*)(d0 + 4) = make_float4(lo[4], lo[5], lo[6], lo[7]);
            *(float4*)d1       = make_float4(hi[0], hi[1], hi[2], hi[3]);
            *(float4*)(d1 + 4) = make_float4(hi[4], hi[5], hi[6], hi[7]);
        }
    }
}

// ------------------------- combine: gather-sum + center + bias + residual --
__global__ __launch_bounds__(256) void combine_kernel(const float* __restrict__ points,
                                                      const float* __restrict__ bc,
                                                      const float* __restrict__ bg,
                                                      float* __restrict__ out) {
    __shared__ float sm[32][133];     // [n_local][o], pad 133 -> conflict-free transpose
    __shared__ int   sidx[32*20];
    int b  = blockIdx.y;
    int n0 = blockIdx.x * 32;
    int tid = threadIdx.x;

    for (int u = tid; u < 32*20; u += 256)
        sidx[u] = g_knn[(b*Nn + n0)*20 + u];
    __syncthreads();

    // phase A: neighbor gather-sum into sm[nl][o]
    int h = tid >> 7, o = tid & 127;
    for (int nl = h; nl < 32; nl += 2) {
        float acc = 0.f;
        #pragma unroll
        for (int k = 0; k < Kk; ++k) {
            int nb = sidx[nl*20 + k];          // global b*N+n index
            acc += g_gT[nb*Cc + o];
        }
        sm[nl][o] = acc;
    }
    __syncthreads();

    // phase B: transposed, coalesced write with center + bias + shortcut
    int w = tid >> 5, l = tid & 31;
    int n = n0 + l;
    #pragma unroll
    for (int oo = 0; oo < 16; ++oo) {
        int o2 = w + oo*8;
        int off = (b*Cc + o2)*Nn + n;
        float biasv = fmaf(20.f, bg[o2], bc[o2]);
        out[off] = (sm[l][o2] + g_center[off] + biasv) * (1.0f / 21.0f) + points[off];
    }
}

// ------------------------- launch -----------------------------------------
extern "C" void kernel_launch(void* const* d_in, const int* in_sizes, int n_in,
                              void* d_out, int out_size) {
    const float* xyz    = (const float*)d_in[0];
    const float* points = (const float*)d_in[1];
    const float* Wc     = (const float*)d_in[2];
    const float* bc     = (const float*)d_in[3];
    const float* Wg     = (const float*)d_in[4];
    const float* bg     = (const float*)d_in[5];
    float* out = (float*)d_out;

    prep_kernel<<<256, 256>>>(xyz, Wc, Wg);
    knn_kernel<<<Bb*Nn/128, 128>>>();
    gemm_kernel<<<dim3(Nn/128, Bb, 2), 256>>>(points);
    combine_kernel<<<dim3(Nn/32, Bb), 256>>>(points, bc, bg, out);
}

// round 4
// speedup vs baseline: 2.8036x; 1.4709x over previous
#include <cuda_runtime.h>

#define Bb 8
#define Nn 4096
#define Cc 128
#define Kk 20

// ------------------------- scratch (device globals, no allocs) -------------
__device__ float4 g_pts4[Bb*Nn];          // x,y,z,norm2
__device__ int    g_knn[Bb*Nn*Kk];        // 20 neighbor indices per point (global b*N+n space)
__device__ float  g_wT[2*Cc*Cc];          // WcT then WgT, [c][o]
__device__ float  g_center[Bb*Cc*Nn];     // Wc @ leaky(p)         [b][o][n]
__device__ float  g_gT[Bb*Nn*Cc];         // (Wg @ leaky(p))^T     [b][n][o]

// ------------------------- prep: pack xyz + transpose weights --------------
__global__ __launch_bounds__(256) void prep_kernel(const float* __restrict__ xyz,
                                                   const float* __restrict__ Wc,
                                                   const float* __restrict__ Wg) {
    int id = blockIdx.x * 256 + threadIdx.x;
    if (id < Bb*Nn) {
        int b = id >> 12;
        int n = id & (Nn - 1);
        const float* p = xyz + b * 3 * Nn;
        float x = p[n], y = p[Nn + n], z = p[2*Nn + n];
        g_pts4[id] = make_float4(x, y, z, fmaf(x, x, fmaf(y, y, z * z)));
    } else {
        int t = id - Bb*Nn;                 // 0 .. 2*128*128-1
        int which = t >> 14;                // 0: Wc, 1: Wg
        int e = t & (Cc*Cc - 1);
        int o = e >> 7, c = e & 127;
        const float* W = which ? Wg : Wc;
        g_wT[which*Cc*Cc + c*Cc + o] = W[o*Cc + c];
    }
}

// ------------------------- KNN (sharded two-pass) --------------------------
// Block: 256 threads = 32 queries x 8 shards. Whole batch (4096 float4, 64KB)
// lives in SMEM. Pass 1: each shard thread keeps the sorted top-21 *keys* of
// its 512-candidate shard (float-only FMNMX chain; no indices). Shard lists
// are merged (early-break, lists sorted) to get tau = 21st-smallest key of the
// query (self included; self's key -|x|^2 is the strict min). Pass 2 rescans
// and collects indices with key <= tau, excluding self, via an smem atomic
// slot counter. Sum over neighbors is order-invariant, so set == answer.
#define KNN_INF  3.402823466e38f
#define KNN_SENT (-3.0e38f)
#define QPB 32
#define SHD 8

__device__ __forceinline__ void ins21(float (&ds)[21], float cd) {
    #pragma unroll
    for (int s = 0; s < 21; ++s) {
        float mn = fminf(cd, ds[s]);
        cd = fmaxf(cd, ds[s]);
        ds[s] = mn;
    }
}

__global__ __launch_bounds__(256) void knn_kernel() {
    extern __shared__ float sraw[];
    float4* tile = (float4*)sraw;                    // Nn+8 float4
    float*  mrg  = sraw + (Nn + 8) * 4;              // QPB*SHD*21 floats
    int*    scnt = (int*)(mrg + QPB*SHD*21);         // QPB ints

    int tid   = threadIdx.x;
    int qloc  = tid >> 3;                            // 0..31
    int shard = tid & 7;
    int q     = blockIdx.x * QPB + qloc;             // global query id
    int base  = q & ~(Nn - 1);                       // batch base (uniform per block)
    int selfj = q & (Nn - 1);

    for (int u = tid; u < Nn; u += 256) tile[u] = g_pts4[base + u];
    if (tid < 8)   tile[Nn + tid] = make_float4(0.f, 0.f, 0.f, 0.f);
    if (tid < QPB) scnt[tid] = 0;
    __syncthreads();

    float4 me = tile[selfj];
    float mx = -2.f * me.x, my = -2.f * me.y, mz = -2.f * me.z;

    // ---------------- pass 1: per-shard sorted top-21 keys ----------------
    float ds[21];
    #pragma unroll
    for (int s = 0; s < 21; ++s) ds[s] = KNN_INF;
    float b0 = KNN_SENT, b1 = KNN_SENT;
    float worst = KNN_INF;

    float4 c = tile[shard];
    #pragma unroll 1
    for (int i = 0; i < Nn/SHD; ++i) {
        float4 nc = tile[(i + 1) * SHD + shard];     // prefetch (padded)
        float d = fmaf(mx, c.x, fmaf(my, c.y, fmaf(mz, c.z, c.w)));
        c = nc;
        bool qq = d < worst;
        if (qq) { b1 = b0; b0 = d; }
        if (__any_sync(0xffffffffu, b1 != KNN_SENT)) {
            ins21(ds, (b1 != KNN_SENT) ? b1 : KNN_INF);
            ins21(ds, (b0 != KNN_SENT) ? b0 : KNN_INF);
            worst = ds[20];
            b0 = KNN_SENT; b1 = KNN_SENT;
        }
    }
    ins21(ds, (b1 != KNN_SENT) ? b1 : KNN_INF);
    ins21(ds, (b0 != KNN_SENT) ? b0 : KNN_INF);

    // dump shard list (sorted ascending) for the merge
    int mb = (qloc * SHD + shard) * 21;
    #pragma unroll
    for (int s = 0; s < 21; ++s) mrg[mb + s] = ds[s];
    __syncwarp();

    // ---------------- merge 8 sorted lists -> tau (21st smallest) ---------
    float tau = 0.f;
    if (shard == 0) {
        float md[21];
        #pragma unroll
        for (int s = 0; s < 21; ++s) md[s] = KNN_INF;
        float w2 = KNN_INF;
        int qb = qloc * SHD * 21;
        #pragma unroll 1
        for (int l = 0; l < SHD; ++l) {
            #pragma unroll 1
            for (int s = 0; s < 21; ++s) {
                float v = mrg[qb + l*21 + s];
                if (v >= w2) break;                  // list sorted: rest can't enter
                ins21(md, v);
                w2 = md[20];
            }
        }
        tau = md[20];
    }
    tau = __shfl_sync(0xffffffffu, tau, (tid & 31) & ~7);

    // ---------------- pass 2: collect indices with key <= tau -------------
    c = tile[shard];
    #pragma unroll 1
    for (int i = 0; i < Nn/SHD; ++i) {
        int j = i * SHD + shard;
        float4 nc = tile[j + SHD];
        float d = fmaf(mx, c.x, fmaf(my, c.y, fmaf(mz, c.z, c.w)));
        c = nc;
        if (d <= tau && j != selfj) {
            int slot = atomicAdd(&scnt[qloc], 1);
            if (slot < Kk) g_knn[q*Kk + slot] = base + j;
        }
    }
}

// ------------------------- fused GEMM: [Wc;Wg] @ leaky(P) ------------------
// grid (N/128, B, 2); z=0 -> center [b][o][n], z=1 -> gT transposed [b][n][o]
__global__ __launch_bounds__(256) void gemm_kernel(const float* __restrict__ points) {
    __shared__ __align__(16) float Ws[32][128];   // [c][o]
    __shared__ __align__(16) float Ps[32][128];   // [c][n]
    int b  = blockIdx.y;
    int n0 = blockIdx.x * 128;
    int which = blockIdx.z;
    const float* WT = g_wT + which * Cc * Cc;
    const float* P  = points + b * Cc * Nn;
    int tid = threadIdx.x;
    int tx = tid & 15, ty = tid >> 4;

    unsigned long long acc[8][4];                 // 8 rows x 4 fp32x2 col-pairs
    #pragma unroll
    for (int r = 0; r < 8; ++r)
        #pragma unroll
        for (int q = 0; q < 4; ++q) acc[r][q] = 0ull;

    for (int kc = 0; kc < Cc; kc += 32) {
        __syncthreads();
        #pragma unroll
        for (int i = 0; i < 4; ++i) {
            int f4 = tid + i * 256;               // 0..1023 float4 slots
            int c = f4 >> 5, n4 = f4 & 31;
            *(float4*)&Ws[c][n4*4] = *(const float4*)(WT + (kc + c)*Cc + n4*4);
            float4 pv = *(const float4*)(P + (kc + c)*Nn + n0 + n4*4);
            pv.x = fmaxf(pv.x, 0.f) + 0.01f * fminf(pv.x, 0.f);
            pv.y = fmaxf(pv.y, 0.f) + 0.01f * fminf(pv.y, 0.f);
            pv.z = fmaxf(pv.z, 0.f) + 0.01f * fminf(pv.z, 0.f);
            pv.w = fmaxf(pv.w, 0.f) + 0.01f * fminf(pv.w, 0.f);
            *(float4*)&Ps[c][n4*4] = pv;
        }
        __syncthreads();
        #pragma unroll
        for (int c = 0; c < 32; ++c) {
            float a[8];
            *(float4*)&a[0] = *(float4*)&Ws[c][ty*8];
            *(float4*)&a[4] = *(float4*)&Ws[c][ty*8 + 4];
            unsigned long long bp[4];
            *(ulonglong2*)&bp[0] = *(ulonglong2*)&Ps[c][tx*8];
            *(ulonglong2*)&bp[2] = *(ulonglong2*)&Ps[c][tx*8 + 4];
            #pragma unroll
            for (int r = 0; r < 8; ++r) {
                unsigned long long av;
                asm("mov.b64 %0, {%1, %1};" : "=l"(av) : "f"(a[r]));
                #pragma unroll
                for (int q = 0; q < 4; ++q)
                    asm("fma.rn.f32x2 %0, %1, %2, %0;"
                        : "+l"(acc[r][q]) : "l"(av), "l"(bp[q]));
            }
        }
    }

    union U { unsigned long long u; float2 f; };
    if (which == 0) {
        #pragma unroll
        for (int r = 0; r < 8; ++r) {
            int o = ty*8 + r;
            float v[8];
            #pragma unroll
            for (int q = 0; q < 4; ++q) { U t; t.u = acc[r][q]; v[2*q] = t.f.x; v[2*q+1] = t.f.y; }
            float* dst = g_center + (b*Cc + o)*Nn + n0 + tx*8;
            *(float4*)dst       = make_float4(v[0], v[1], v[2], v[3]);
            *(float4*)(dst + 4) = make_float4(v[4], v[5], v[6], v[7]);
        }
    } else {
        #pragma unroll
        for (int q = 0; q < 4; ++q) {
            float lo[8], hi[8];
            #pragma unroll
            for (int r = 0; r < 8; ++r) { U t; t.u = acc[r][q]; lo[r] = t.f.x; hi[r] = t.f.y; }
            int n = n0 + tx*8 + 2*q;
            float* d0 = g_gT + (b*Nn + n    )*Cc + ty*8;
            float* d1 = g_gT + (b*Nn + n + 1)*Cc + ty*8;
            *(float4*)d0       = make_float4(lo[0], lo[1], lo[2], lo[3]);
            *(float4*)(d0 + 4) = make_float4(lo[4], lo[5], lo[6], lo[7]);
            *(float4*)d1       = make_float4(hi[0], hi[1], hi[2], hi[3]);
            *(float4*)(d1 + 4) = make_float4(hi[4], hi[5], hi[6], hi[7]);
        }
    }
}

// ------------------------- combine: gather-sum + center + bias + residual --
__global__ __launch_bounds__(256) void combine_kernel(const float* __restrict__ points,
                                                      const float* __restrict__ bc,
                                                      const float* __restrict__ bg,
                                                      float* __restrict__ out) {
    __shared__ float sm[32][133];     // [n_local][o], pad 133 -> conflict-free transpose
    __shared__ int   sidx[32*20];
    int b  = blockIdx.y;
    int n0 = blockIdx.x * 32;
    int tid = threadIdx.x;

    for (int u = tid; u < 32*20; u += 256)
        sidx[u] = g_knn[(b*Nn + n0)*20 + u];
    __syncthreads();

    // phase A: neighbor gather-sum into sm[nl][o]
    int h = tid >> 7, o = tid & 127;
    for (int nl = h; nl < 32; nl += 2) {
        float acc = 0.f;
        #pragma unroll
        for (int k = 0; k < Kk; ++k) {
            int nb = sidx[nl*20 + k];          // global b*N+n index
            acc += g_gT[nb*Cc + o];
        }
        sm[nl][o] = acc;
    }
    __syncthreads();

    // phase B: transposed, coalesced write with center + bias + shortcut
    int w = tid >> 5, l = tid & 31;
    int n = n0 + l;
    #pragma unroll
    for (int oo = 0; oo < 16; ++oo) {
        int o2 = w + oo*8;
        int off = (b*Cc + o2)*Nn + n;
        float biasv = fmaf(20.f, bg[o2], bc[o2]);
        out[off] = (sm[l][o2] + g_center[off] + biasv) * (1.0f / 21.0f) + points[off];
    }
}

// ------------------------- launch -----------------------------------------
extern "C" void kernel_launch(void* const* d_in, const int* in_sizes, int n_in,
                              void* d_out, int out_size) {
    const float* xyz    = (const float*)d_in[0];
    const float* points = (const float*)d_in[1];
    const float* Wc     = (const float*)d_in[2];
    const float* bc     = (const float*)d_in[3];
    const float* Wg     = (const float*)d_in[4];
    const float* bg     = (const float*)d_in[5];
    float* out = (float*)d_out;

    int knn_smem = (Nn + 8) * 16 + QPB * SHD * 21 * 4 + QPB * 4;
    cudaFuncSetAttribute(knn_kernel, cudaFuncAttributeMaxDynamicSharedMemorySize, knn_smem);

    prep_kernel<<<256, 256>>>(xyz, Wc, Wg);
    knn_kernel<<<Bb*Nn/QPB, 256, knn_smem>>>();
    gemm_kernel<<<dim3(Nn/128, Bb, 2), 256>>>(points);
    combine_kernel<<<dim3(Nn/32, Bb), 256>>>(points, bc, bg, out);
}

// round 5
// speedup vs baseline: 3.2295x; 1.1519x over previous
#include <cuda_runtime.h>

#define Bb 8
#define Nn 4096
#define Cc 128
#define Kk 20

// ------------------------- scratch (device globals, no allocs) -------------
__device__ float4 g_pts4[Bb*Nn];          // x,y,z,norm2
__device__ int    g_knn[Bb*Nn*Kk];        // 20 neighbor indices per point (global b*N+n space)
__device__ float  g_wT[2*Cc*Cc];          // WcT then WgT, [c][o]
__device__ float  g_center[Bb*Cc*Nn];     // Wc @ leaky(p)         [b][o][n]
__device__ float  g_gT[Bb*Nn*Cc];         // (Wg @ leaky(p))^T     [b][n][o]

// ------------------------- prep: pack xyz + transpose weights --------------
__global__ __launch_bounds__(256) void prep_kernel(const float* __restrict__ xyz,
                                                   const float* __restrict__ Wc,
                                                   const float* __restrict__ Wg) {
    int id = blockIdx.x * 256 + threadIdx.x;
    if (id < Bb*Nn) {
        int b = id >> 12;
        int n = id & (Nn - 1);
        const float* p = xyz + b * 3 * Nn;
        float x = p[n], y = p[Nn + n], z = p[2*Nn + n];
        g_pts4[id] = make_float4(x, y, z, fmaf(x, x, fmaf(y, y, z * z)));
    } else {
        int t = id - Bb*Nn;                 // 0 .. 2*128*128-1
        int which = t >> 14;                // 0: Wc, 1: Wg
        int e = t & (Cc*Cc - 1);
        int o = e >> 7, c = e & 127;
        const float* W = which ? Wg : Wc;
        g_wT[which*Cc*Cc + c*Cc + o] = W[o*Cc + c];
    }
}

// ------------------------- KNN (sharded two-pass, smem staging) ------------
// Block: 256 threads = 64 queries x 4 shards. Whole batch tile (64KB) in SMEM.
// Pass 1: per shard-thread top-21 KEYS only (float FMNMX network). Qualifying
// keys are staged in a 16-deep SMEM buffer (STS, depth-independent cost);
// a warp vote every 4 candidates flushes at >=13 pending (capacity-safe).
// Merge per query -> tau = 21st-smallest key (self incl; self key is strict
// min). Pass 2 rescans, collects indices with key <= tau (excluding self)
// via smem atomic slot counter. Neighbor-sum is order-invariant.
#define KNN_INF  3.402823466e38f
#define QPB 64
#define SHD 4
#define STG 16

__device__ __forceinline__ void ins21(float (&ds)[21], float cd) {
    #pragma unroll
    for (int s = 0; s < 21; ++s) {
        float mn = fminf(cd, ds[s]);
        cd = fmaxf(cd, ds[s]);
        ds[s] = mn;
    }
}

__global__ __launch_bounds__(256) void knn_kernel() {
    extern __shared__ float sraw[];
    float4* tile  = (float4*)sraw;                     // Nn float4 (64KB)
    float*  stage = sraw + Nn*4;                       // 256*STG floats
    float*  mrg   = stage + 256*STG;                   // QPB*SHD*21 floats
    int*    scnt  = (int*)(mrg + QPB*SHD*21);          // QPB ints

    int tid   = threadIdx.x;
    int qloc  = tid >> 2;                              // 0..63
    int shard = tid & 3;
    int q     = blockIdx.x * QPB + qloc;
    int base  = q & ~(Nn - 1);
    int selfj = q & (Nn - 1);

    for (int u = tid; u < Nn; u += 256) tile[u] = g_pts4[base + u];
    if (tid < QPB) scnt[tid] = 0;
    __syncthreads();

    float4 me = tile[selfj];
    float mx = -2.f * me.x, my = -2.f * me.y, mz = -2.f * me.z;

    // ---------------- pass 1: per-shard sorted top-21 keys ----------------
    float ds[21];
    #pragma unroll
    for (int s = 0; s < 21; ++s) ds[s] = KNN_INF;
    float worst = KNN_INF;
    int cnt = 0;
    float* st = stage + tid * STG;

    #pragma unroll 1
    for (int i0 = 0; i0 < Nn/SHD; i0 += 4) {
        #pragma unroll
        for (int u2 = 0; u2 < 4; ++u2) {
            float4 c = tile[(i0 + u2) * SHD + shard];
            float d = fmaf(mx, c.x, fmaf(my, c.y, fmaf(mz, c.z, c.w)));
            if (d < worst) { st[cnt] = d; ++cnt; }
        }
        if (__any_sync(0xffffffffu, cnt >= STG - 3)) {
            #pragma unroll 1
            for (int u = 0; u < STG; ++u) {
                float v = st[u];
                ins21(ds, (u < cnt) ? v : KNN_INF);
            }
            worst = ds[20];
            cnt = 0;
        }
    }
    #pragma unroll 1
    for (int u = 0; u < STG; ++u) {                    // final drain
        float v = st[u];
        ins21(ds, (u < cnt) ? v : KNN_INF);
    }

    // dump shard list (sorted ascending) for the merge
    int mb = (qloc * SHD + shard) * 21;
    #pragma unroll
    for (int s = 0; s < 21; ++s) mrg[mb + s] = ds[s];
    __syncwarp();

    // ---------------- merge SHD sorted lists -> tau (21st smallest) -------
    float tau = 0.f;
    if (shard == 0) {
        float md[21];
        #pragma unroll
        for (int s = 0; s < 21; ++s) md[s] = KNN_INF;
        float w2 = KNN_INF;
        int qb = qloc * SHD * 21;
        #pragma unroll 1
        for (int l = 0; l < SHD; ++l) {
            #pragma unroll 1
            for (int s = 0; s < 21; ++s) {
                float v = mrg[qb + l*21 + s];
                if (v >= w2) break;                    // list sorted: rest can't enter
                ins21(md, v);
                w2 = md[20];
            }
        }
        tau = md[20];
    }
    tau = __shfl_sync(0xffffffffu, tau, (tid & 31) & ~3);

    // ---------------- pass 2: collect indices with key <= tau -------------
    #pragma unroll 1
    for (int i0 = 0; i0 < Nn/SHD; i0 += 4) {
        #pragma unroll
        for (int u2 = 0; u2 < 4; ++u2) {
            int j = (i0 + u2) * SHD + shard;
            float4 c = tile[j];
            float d = fmaf(mx, c.x, fmaf(my, c.y, fmaf(mz, c.z, c.w)));
            if (d <= tau && j != selfj) {
                int slot = atomicAdd(&scnt[qloc], 1);
                if (slot < Kk) g_knn[q*Kk + slot] = base + j;
            }
        }
    }
}

// ------------------------- fused GEMM: [Wc;Wg] @ leaky(P) ------------------
// grid (N/128, B, 2); z=0 -> center [b][o][n], z=1 -> gT transposed [b][n][o]
__global__ __launch_bounds__(256) void gemm_kernel(const float* __restrict__ points) {
    __shared__ __align__(16) float Ws[32][128];   // [c][o]
    __shared__ __align__(16) float Ps[32][128];   // [c][n]
    int b  = blockIdx.y;
    int n0 = blockIdx.x * 128;
    int which = blockIdx.z;
    const float* WT = g_wT + which * Cc * Cc;
    const float* P  = points + b * Cc * Nn;
    int tid = threadIdx.x;
    int tx = tid & 15, ty = tid >> 4;

    unsigned long long acc[8][4];                 // 8 rows x 4 fp32x2 col-pairs
    #pragma unroll
    for (int r = 0; r < 8; ++r)
        #pragma unroll
        for (int q = 0; q < 4; ++q) acc[r][q] = 0ull;

    for (int kc = 0; kc < Cc; kc += 32) {
        __syncthreads();
        #pragma unroll
        for (int i = 0; i < 4; ++i) {
            int f4 = tid + i * 256;               // 0..1023 float4 slots
            int c = f4 >> 5, n4 = f4 & 31;
            *(float4*)&Ws[c][n4*4] = *(const float4*)(WT + (kc + c)*Cc + n4*4);
            float4 pv = *(const float4*)(P + (kc + c)*Nn + n0 + n4*4);
            pv.x = fmaxf(pv.x, 0.f) + 0.01f * fminf(pv.x, 0.f);
            pv.y = fmaxf(pv.y, 0.f) + 0.01f * fminf(pv.y, 0.f);
            pv.z = fmaxf(pv.z, 0.f) + 0.01f * fminf(pv.z, 0.f);
            pv.w = fmaxf(pv.w, 0.f) + 0.01f * fminf(pv.w, 0.f);
            *(float4*)&Ps[c][n4*4] = pv;
        }
        __syncthreads();
        #pragma unroll
        for (int c = 0; c < 32; ++c) {
            float a[8];
            *(float4*)&a[0] = *(float4*)&Ws[c][ty*8];
            *(float4*)&a[4] = *(float4*)&Ws[c][ty*8 + 4];
            unsigned long long bp[4];
            *(ulonglong2*)&bp[0] = *(ulonglong2*)&Ps[c][tx*8];
            *(ulonglong2*)&bp[2] = *(ulonglong2*)&Ps[c][tx*8 + 4];
            #pragma unroll
            for (int r = 0; r < 8; ++r) {
                unsigned long long av;
                asm("mov.b64 %0, {%1, %1};" : "=l"(av) : "f"(a[r]));
                #pragma unroll
                for (int q = 0; q < 4; ++q)
                    asm("fma.rn.f32x2 %0, %1, %2, %0;"
                        : "+l"(acc[r][q]) : "l"(av), "l"(bp[q]));
            }
        }
    }

    union U { unsigned long long u; float2 f; };
    if (which == 0) {
        #pragma unroll
        for (int r = 0; r < 8; ++r) {
            int o = ty*8 + r;
            float v[8];
            #pragma unroll
            for (int q = 0; q < 4; ++q) { U t; t.u = acc[r][q]; v[2*q] = t.f.x; v[2*q+1] = t.f.y; }
            float* dst = g_center + (b*Cc + o)*Nn + n0 + tx*8;
            *(float4*)dst       = make_float4(v[0], v[1], v[2], v[3]);
            *(float4*)(dst + 4) = make_float4(v[4], v[5], v[6], v[7]);
        }
    } else {
        #pragma unroll
        for (int q = 0; q < 4; ++q) {
            float lo[8], hi[8];
            #pragma unroll
            for (int r = 0; r < 8; ++r) { U t; t.u = acc[r][q]; lo[r] = t.f.x; hi[r] = t.f.y; }
            int n = n0 + tx*8 + 2*q;
            float* d0 = g_gT + (b*Nn + n    )*Cc + ty*8;
            float* d1 = g_gT + (b*Nn + n + 1)*Cc + ty*8;
            *(float4*)d0       = make_float4(lo[0], lo[1], lo[2], lo[3]);
            *(float4*)(d0 + 4) = make_float4(lo[4], lo[5], lo[6], lo[7]);
            *(float4*)d1       = make_float4(hi[0], hi[1], hi[2], hi[3]);
            *(float4*)(d1 + 4) = make_float4(hi[4], hi[5], hi[6], hi[7]);
        }
    }
}

// ------------------------- combine: gather-sum + center + bias + residual --
__global__ __launch_bounds__(256) void combine_kernel(const float* __restrict__ points,
                                                      const float* __restrict__ bc,
                                                      const float* __restrict__ bg,
                                                      float* __restrict__ out) {
    __shared__ float sm[32][133];     // [n_local][o], pad 133 -> conflict-free transpose
    __shared__ int   sidx[32*20];
    int b  = blockIdx.y;
    int n0 = blockIdx.x * 32;
    int tid = threadIdx.x;

    for (int u = tid; u < 32*20; u += 256)
        sidx[u] = g_knn[(b*Nn + n0)*20 + u];
    __syncthreads();

    // phase A: neighbor gather-sum into sm[nl][o]
    int h = tid >> 7, o = tid & 127;
    for (int nl = h; nl < 32; nl += 2) {
        float acc = 0.f;
        #pragma unroll
        for (int k = 0; k < Kk; ++k) {
            int nb = sidx[nl*20 + k];          // global b*N+n index
            acc += g_gT[nb*Cc + o];
        }
        sm[nl][o] = acc;
    }
    __syncthreads();

    // phase B: transposed, coalesced write with center + bias + shortcut
    int w = tid >> 5, l = tid & 31;
    int n = n0 + l;
    #pragma unroll
    for (int oo = 0; oo < 16; ++oo) {
        int o2 = w + oo*8;
        int off = (b*Cc + o2)*Nn + n;
        float biasv = fmaf(20.f, bg[o2], bc[o2]);
        out[off] = (sm[l][o2] + g_center[off] + biasv) * (1.0f / 21.0f) + points[off];
    }
}

// ------------------------- launch -----------------------------------------
extern "C" void kernel_launch(void* const* d_in, const int* in_sizes, int n_in,
                              void* d_out, int out_size) {
    const float* xyz    = (const float*)d_in[0];
    const float* points = (const float*)d_in[1];
    const float* Wc     = (const float*)d_in[2];
    const float* bc     = (const float*)d_in[3];
    const float* Wg     = (const float*)d_in[4];
    const float* bg     = (const float*)d_in[5];
    float* out = (float*)d_out;

    int knn_smem = Nn*16 + 256*STG*4 + QPB*SHD*21*4 + QPB*4;
    cudaFuncSetAttribute(knn_kernel, cudaFuncAttributeMaxDynamicSharedMemorySize, knn_smem);

    prep_kernel<<<256, 256>>>(xyz, Wc, Wg);
    knn_kernel<<<Bb*Nn/QPB, 256, knn_smem>>>();
    gemm_kernel<<<dim3(Nn/128, Bb, 2), 256>>>(points);
    combine_kernel<<<dim3(Nn/32, Bb), 256>>>(points, bc, bg, out);
}

// round 6
// speedup vs baseline: 3.3679x; 1.0429x over previous
#include <cuda_runtime.h>

#define Bb 8
#define Nn 4096
#define Cc 128
#define Kk 20

// ------------------------- scratch (device globals, no allocs) -------------
__device__ float4 g_pts4[Bb*Nn];          // x,y,z,norm2
__device__ int    g_knn[Bb*Nn*Kk];        // 20 neighbor indices per point (global b*N+n space)
__device__ float  g_wT[2*Cc*Cc];          // WcT then WgT, [c][o]
__device__ float  g_center[Bb*Cc*Nn];     // Wc @ leaky(p)         [b][o][n]
__device__ float  g_gT[Bb*Nn*Cc];         // (Wg @ leaky(p))^T     [b][n][o]

// ------------------------- prep: pack xyz + transpose weights --------------
__global__ __launch_bounds__(256) void prep_kernel(const float* __restrict__ xyz,
                                                   const float* __restrict__ Wc,
                                                   const float* __restrict__ Wg) {
    int id = blockIdx.x * 256 + threadIdx.x;
    if (id < Bb*Nn) {
        int b = id >> 12;
        int n = id & (Nn - 1);
        const float* p = xyz + b * 3 * Nn;
        float x = p[n], y = p[Nn + n], z = p[2*Nn + n];
        g_pts4[id] = make_float4(x, y, z, fmaf(x, x, fmaf(y, y, z * z)));
    } else {
        int t = id - Bb*Nn;                 // 0 .. 2*128*128-1
        int which = t >> 14;                // 0: Wc, 1: Wg
        int e = t & (Cc*Cc - 1);
        int o = e >> 7, c = e & 127;
        const float* W = which ? Wg : Wc;
        g_wT[which*Cc*Cc + c*Cc + o] = W[o*Cc + c];
    }
}

// ------------------------- KNN (sharded two-pass, smem staging) ------------
// Block: 256 threads = 64 queries x 4 shards. Whole batch tile (64KB) in SMEM.
// Pass 1: per shard-thread top-21 KEYS only (float FMNMX network). Qualifying
// keys are staged in a 16-deep SMEM buffer (STS, depth-independent cost);
// a warp vote every 4 candidates flushes at >=13 pending (capacity-safe).
// Staging stride is 17 floats (odd) so (lane*17 + cnt) mod 32 is bijective in
// lane -> staging STS and flush LDS are bank-conflict-free (stride 16 was a
// 16-way conflict on every access).
// Merge per query -> tau = 21st-smallest key (self incl; self key is strict
// min). Pass 2 rescans, collects indices with key <= tau (excluding self)
// via smem atomic slot counter. Neighbor-sum is order-invariant.
#define KNN_INF  3.402823466e38f
#define QPB 64
#define SHD 4
#define STG 16
#define STGP 17

__device__ __forceinline__ void ins21(float (&ds)[21], float cd) {
    #pragma unroll
    for (int s = 0; s < 21; ++s) {
        float mn = fminf(cd, ds[s]);
        cd = fmaxf(cd, ds[s]);
        ds[s] = mn;
    }
}

__global__ __launch_bounds__(256) void knn_kernel() {
    extern __shared__ float sraw[];
    float4* tile  = (float4*)sraw;                     // Nn float4 (64KB)
    float*  stage = sraw + Nn*4;                       // 256*STGP floats (padded stride)
    float*  mrg   = stage + 256*STGP;                  // QPB*SHD*21 floats
    int*    scnt  = (int*)(mrg + QPB*SHD*21);          // QPB ints

    int tid   = threadIdx.x;
    int qloc  = tid >> 2;                              // 0..63
    int shard = tid & 3;
    int q     = blockIdx.x * QPB + qloc;
    int base  = q & ~(Nn - 1);
    int selfj = q & (Nn - 1);

    for (int u = tid; u < Nn; u += 256) tile[u] = g_pts4[base + u];
    if (tid < QPB) scnt[tid] = 0;
    __syncthreads();

    float4 me = tile[selfj];
    float mx = -2.f * me.x, my = -2.f * me.y, mz = -2.f * me.z;

    // ---------------- pass 1: per-shard sorted top-21 keys ----------------
    float ds[21];
    #pragma unroll
    for (int s = 0; s < 21; ++s) ds[s] = KNN_INF;
    float worst = KNN_INF;
    int cnt = 0;
    float* st = stage + tid * STGP;

    #pragma unroll 1
    for (int i0 = 0; i0 < Nn/SHD; i0 += 4) {
        #pragma unroll
        for (int u2 = 0; u2 < 4; ++u2) {
            float4 c = tile[(i0 + u2) * SHD + shard];
            float d = fmaf(mx, c.x, fmaf(my, c.y, fmaf(mz, c.z, c.w)));
            if (d < worst) { st[cnt] = d; ++cnt; }
        }
        if (__any_sync(0xffffffffu, cnt >= STG - 3)) {
            #pragma unroll 1
            for (int u = 0; u < STG; ++u) {
                float v = st[u];
                ins21(ds, (u < cnt) ? v : KNN_INF);
            }
            worst = ds[20];
            cnt = 0;
        }
    }
    #pragma unroll 1
    for (int u = 0; u < STG; ++u) {                    // final drain
        float v = st[u];
        ins21(ds, (u < cnt) ? v : KNN_INF);
    }

    // dump shard list (sorted ascending) for the merge
    int mb = (qloc * SHD + shard) * 21;
    #pragma unroll
    for (int s = 0; s < 21; ++s) mrg[mb + s] = ds[s];
    __syncwarp();

    // ---------------- merge SHD sorted lists -> tau (21st smallest) -------
    float tau = 0.f;
    if (shard == 0) {
        float md[21];
        #pragma unroll
        for (int s = 0; s < 21; ++s) md[s] = KNN_INF;
        float w2 = KNN_INF;
        int qb = qloc * SHD * 21;
        #pragma unroll 1
        for (int l = 0; l < SHD; ++l) {
            #pragma unroll 1
            for (int s = 0; s < 21; ++s) {
                float v = mrg[qb + l*21 + s];
                if (v >= w2) break;                    // list sorted: rest can't enter
                ins21(md, v);
                w2 = md[20];
            }
        }
        tau = md[20];
    }
    tau = __shfl_sync(0xffffffffu, tau, (tid & 31) & ~3);

    // ---------------- pass 2: collect indices with key <= tau -------------
    #pragma unroll 1
    for (int i0 = 0; i0 < Nn/SHD; i0 += 4) {
        #pragma unroll
        for (int u2 = 0; u2 < 4; ++u2) {
            int j = (i0 + u2) * SHD + shard;
            float4 c = tile[j];
            float d = fmaf(mx, c.x, fmaf(my, c.y, fmaf(mz, c.z, c.w)));
            if (d <= tau && j != selfj) {
                int slot = atomicAdd(&scnt[qloc], 1);
                if (slot < Kk) g_knn[q*Kk + slot] = base + j;
            }
        }
    }
}

// ------------------------- fused GEMM: [Wc;Wg] @ leaky(P) ------------------
// grid (N/128, B, 2); z=0 -> center [b][o][n], z=1 -> gT transposed [b][n][o]
__global__ __launch_bounds__(256) void gemm_kernel(const float* __restrict__ points) {
    __shared__ __align__(16) float Ws[32][128];   // [c][o]
    __shared__ __align__(16) float Ps[32][128];   // [c][n]
    int b  = blockIdx.y;
    int n0 = blockIdx.x * 128;
    int which = blockIdx.z;
    const float* WT = g_wT + which * Cc * Cc;
    const float* P  = points + b * Cc * Nn;
    int tid = threadIdx.x;
    int tx = tid & 15, ty = tid >> 4;

    unsigned long long acc[8][4];                 // 8 rows x 4 fp32x2 col-pairs
    #pragma unroll
    for (int r = 0; r < 8; ++r)
        #pragma unroll
        for (int q = 0; q < 4; ++q) acc[r][q] = 0ull;

    for (int kc = 0; kc < Cc; kc += 32) {
        __syncthreads();
        #pragma unroll
        for (int i = 0; i < 4; ++i) {
            int f4 = tid + i * 256;               // 0..1023 float4 slots
            int c = f4 >> 5, n4 = f4 & 31;
            *(float4*)&Ws[c][n4*4] = *(const float4*)(WT + (kc + c)*Cc + n4*4);
            float4 pv = *(const float4*)(P + (kc + c)*Nn + n0 + n4*4);
            pv.x = fmaxf(pv.x, 0.f) + 0.01f * fminf(pv.x, 0.f);
            pv.y = fmaxf(pv.y, 0.f) + 0.01f * fminf(pv.y, 0.f);
            pv.z = fmaxf(pv.z, 0.f) + 0.01f * fminf(pv.z, 0.f);
            pv.w = fmaxf(pv.w, 0.f) + 0.01f * fminf(pv.w, 0.f);
            *(float4*)&Ps[c][n4*4] = pv;
        }
        __syncthreads();
        #pragma unroll
        for (int c = 0; c < 32; ++c) {
            float a[8];
            *(float4*)&a[0] = *(float4*)&Ws[c][ty*8];
            *(float4*)&a[4] = *(float4*)&Ws[c][ty*8 + 4];
            unsigned long long bp[4];
            *(ulonglong2*)&bp[0] = *(ulonglong2*)&Ps[c][tx*8];
            *(ulonglong2*)&bp[2] = *(ulonglong2*)&Ps[c][tx*8 + 4];
            #pragma unroll
            for (int r = 0; r < 8; ++r) {
                unsigned long long av;
                asm("mov.b64 %0, {%1, %1};" : "=l"(av) : "f"(a[r]));
                #pragma unroll
                for (int q = 0; q < 4; ++q)
                    asm("fma.rn.f32x2 %0, %1, %2, %0;"
                        : "+l"(acc[r][q]) : "l"(av), "l"(bp[q]));
            }
        }
    }

    union U { unsigned long long u; float2 f; };
    if (which == 0) {
        #pragma unroll
        for (int r = 0; r < 8; ++r) {
            int o = ty*8 + r;
            float v[8];
            #pragma unroll
            for (int q = 0; q < 4; ++q) { U t; t.u = acc[r][q]; v[2*q] = t.f.x; v[2*q+1] = t.f.y; }
            float* dst = g_center + (b*Cc + o)*Nn + n0 + tx*8;
            *(float4*)dst       = make_float4(v[0], v[1], v[2], v[3]);
            *(float4*)(dst + 4) = make_float4(v[4], v[5], v[6], v[7]);
        }
    } else {
        #pragma unroll
        for (int q = 0; q < 4; ++q) {
            float lo[8], hi[8];
            #pragma unroll
            for (int r = 0; r < 8; ++r) { U t; t.u = acc[r][q]; lo[r] = t.f.x; hi[r] = t.f.y; }
            int n = n0 + tx*8 + 2*q;
            float* d0 = g_gT + (b*Nn + n    )*Cc + ty*8;
            float* d1 = g_gT + (b*Nn + n + 1)*Cc + ty*8;
            *(float4*)d0       = make_float4(lo[0], lo[1], lo[2], lo[3]);
            *(float4*)(d0 + 4) = make_float4(lo[4], lo[5], lo[6], lo[7]);
            *(float4*)d1       = make_float4(hi[0], hi[1], hi[2], hi[3]);
            *(float4*)(d1 + 4) = make_float4(hi[4], hi[5], hi[6], hi[7]);
        }
    }
}

// ------------------------- combine: gather-sum + center + bias + residual --
__global__ __launch_bounds__(256) void combine_kernel(const float* __restrict__ points,
                                                      const float* __restrict__ bc,
                                                      const float* __restrict__ bg,
                                                      float* __restrict__ out) {
    __shared__ float sm[32][133];     // [n_local][o], pad 133 -> conflict-free transpose
    __shared__ int   sidx[32*20];
    int b  = blockIdx.y;
    int n0 = blockIdx.x * 32;
    int tid = threadIdx.x;

    for (int u = tid; u < 32*20; u += 256)
        sidx[u] = g_knn[(b*Nn + n0)*20 + u];
    __syncthreads();

    // phase A: neighbor gather-sum into sm[nl][o]
    int h = tid >> 7, o = tid & 127;
    for (int nl = h; nl < 32; nl += 2) {
        float acc = 0.f;
        #pragma unroll
        for (int k = 0; k < Kk; ++k) {
            int nb = sidx[nl*20 + k];          // global b*N+n index
            acc += g_gT[nb*Cc + o];
        }
        sm[nl][o] = acc;
    }
    __syncthreads();

    // phase B: transposed, coalesced write with center + bias + shortcut
    int w = tid >> 5, l = tid & 31;
    int n = n0 + l;
    #pragma unroll
    for (int oo = 0; oo < 16; ++oo) {
        int o2 = w + oo*8;
        int off = (b*Cc + o2)*Nn + n;
        float biasv = fmaf(20.f, bg[o2], bc[o2]);
        out[off] = (sm[l][o2] + g_center[off] + biasv) * (1.0f / 21.0f) + points[off];
    }
}

// ------------------------- launch -----------------------------------------
extern "C" void kernel_launch(void* const* d_in, const int* in_sizes, int n_in,
                              void* d_out, int out_size) {
    const float* xyz    = (const float*)d_in[0];
    const float* points = (const float*)d_in[1];
    const float* Wc     = (const float*)d_in[2];
    const float* bc     = (const float*)d_in[3];
    const float* Wg     = (const float*)d_in[4];
    const float* bg     = (const float*)d_in[5];
    float* out = (float*)d_out;

    int knn_smem = Nn*16 + 256*STGP*4 + QPB*SHD*21*4 + QPB*4;
    cudaFuncSetAttribute(knn_kernel, cudaFuncAttributeMaxDynamicSharedMemorySize, knn_smem);

    prep_kernel<<<256, 256>>>(xyz, Wc, Wg);
    knn_kernel<<<Bb*Nn/QPB, 256, knn_smem>>>();
    gemm_kernel<<<dim3(Nn/128, Bb, 2), 256>>>(points);
    combine_kernel<<<dim3(Nn/32, Bb), 256>>>(points, bc, bg, out);
}

// round 7
// speedup vs baseline: 3.7053x; 1.1002x over previous
#include <cuda_runtime.h>

#define Bb 8
#define Nn 4096
#define Cc 128
#define Kk 20

// ------------------------- scratch (device globals, no allocs) -------------
__device__ int    g_knn[Bb*Nn*Kk];        // 20 neighbor indices per point (global b*N+n space)
__device__ float  g_wT[2*Cc*Cc];          // WcT then WgT, [c][o]
__device__ float  g_center[Bb*Cc*Nn];     // Wc @ leaky(p)         [b][o][n]
__device__ float  g_gT[Bb*Nn*Cc];         // (Wg @ leaky(p))^T     [b][n][o]

// ------------------------- prep: transpose weights -------------------------
__global__ __launch_bounds__(256) void prep_kernel(const float* __restrict__ Wc,
                                                   const float* __restrict__ Wg) {
    int t = blockIdx.x * 256 + threadIdx.x;   // 0 .. 2*128*128-1
    int which = t >> 14;                      // 0: Wc, 1: Wg
    int e = t & (Cc*Cc - 1);
    int o = e >> 7, c = e & 127;
    const float* W = which ? Wg : Wc;
    g_wT[which*Cc*Cc + c*Cc + o] = W[o*Cc + c];
}

// ------------------------- KNN (single-pass, lane-per-query) ---------------
// Block: 128 threads = 128 queries; whole batch tile (64KB) in SMEM, packed
// from xyz in-kernel. Every lane processes the SAME candidate j each step ->
// tile[j] is a broadcast LDS (16B unique). Each lane keeps a sorted top-21
// of (key, index) pairs in registers (self included: self key -|x|^2 is the
// strict minimum -> slot 0). Qualifying pairs go to a 16-deep SMEM staging
// buffer (stride 17: conflict-light); a warp vote every 4 candidates flushes
// at >=13 pending (capacity-safe). Flush inserts via an FMNMX value chain +
// FSETP->SEL index chain (all lat-4, branch-free; invalid slots enter as
// +INF = no-op). No second pass: indices come straight from the register list.
#define KNN_INF  3.402823466e38f
#define KTHR 128
#define KSTG 16
#define KSTGP 17

__device__ __forceinline__ void pair_ins(float (&ds)[21], int (&ix)[21],
                                         float cd, int ci) {
    #pragma unroll
    for (int s = 0; s < 21; ++s) {
        bool t   = cd < ds[s];               // strict: earlier insert wins ties
        float mn = fminf(cd, ds[s]);
        float mx = fmaxf(cd, ds[s]);
        int  ni  = t ? ci : ix[s];
        ci       = t ? ix[s] : ci;
        ds[s] = mn; ix[s] = ni; cd = mx;
    }
}

__global__ __launch_bounds__(KTHR) void knn_kernel(const float* __restrict__ xyz) {
    extern __shared__ float sraw[];
    float4* tile = (float4*)sraw;                      // Nn float4 (64KB)
    float*  stgd = sraw + Nn*4;                        // KTHR*KSTGP floats
    int*    stgi = (int*)(stgd + KTHR*KSTGP);          // KTHR*KSTGP ints

    int tid = threadIdx.x;
    int q0  = blockIdx.x * KTHR;                       // first query (32 blocks/batch)
    int b   = q0 >> 12;
    const float* px = xyz + b * 3 * Nn;

    // pack this batch's xyz -> (x,y,z,|x|^2) tile
    for (int n = tid; n < Nn; n += KTHR) {
        float x = px[n], y = px[Nn + n], z = px[2*Nn + n];
        tile[n] = make_float4(x, y, z, fmaf(x, x, fmaf(y, y, z * z)));
    }
    __syncthreads();

    int selfn = (q0 & (Nn - 1)) + tid;                 // local index of own query
    float4 me = tile[selfn];
    float mx = -2.f * me.x, my = -2.f * me.y, mz = -2.f * me.z;

    float ds[21]; int ix[21];
    #pragma unroll
    for (int s = 0; s < 21; ++s) { ds[s] = KNN_INF; ix[s] = 0; }
    float worst = KNN_INF;
    int cnt = 0;
    float* sd = stgd + tid * KSTGP;
    int*   si = stgi + tid * KSTGP;

    #pragma unroll 1
    for (int j0 = 0; j0 < Nn; j0 += 4) {
        #pragma unroll
        for (int u = 0; u < 4; ++u) {
            int j = j0 + u;
            float4 c = tile[j];                        // broadcast across warp
            // rank key: |xj|^2 - 2*dot(xi,xj)  (same ordering as squared dist)
            float d = fmaf(mx, c.x, fmaf(my, c.y, fmaf(mz, c.z, c.w)));
            if (d < worst) { sd[cnt] = d; si[cnt] = j; ++cnt; }
        }
        if (__any_sync(0xffffffffu, cnt >= KSTG - 3)) {
            #pragma unroll 1
            for (int u = 0; u < KSTG; ++u) {
                float vd = sd[u]; int vi = si[u];
                pair_ins(ds, ix, (u < cnt) ? vd : KNN_INF, vi);
            }
            worst = ds[20];
            cnt = 0;
        }
    }
    #pragma unroll 1
    for (int u = 0; u < KSTG; ++u) {                   // final drain
        float vd = sd[u]; int vi = si[u];
        pair_ins(ds, ix, (u < cnt) ? vd : KNN_INF, vi);
    }

    int gq = q0 + tid;
    int base = q0 & ~(Nn - 1);
    #pragma unroll
    for (int s = 0; s < 20; ++s) g_knn[gq*Kk + s] = base + ix[s + 1];  // drop self
}

// ------------------------- fused GEMM: [Wc;Wg] @ leaky(P) ------------------
// grid (N/128, B, 2); z=0 -> center [b][o][n], z=1 -> gT transposed [b][n][o]
__global__ __launch_bounds__(256) void gemm_kernel(const float* __restrict__ points) {
    __shared__ __align__(16) float Ws[32][128];   // [c][o]
    __shared__ __align__(16) float Ps[32][128];   // [c][n]
    int b  = blockIdx.y;
    int n0 = blockIdx.x * 128;
    int which = blockIdx.z;
    const float* WT = g_wT + which * Cc * Cc;
    const float* P  = points + b * Cc * Nn;
    int tid = threadIdx.x;
    int tx = tid & 15, ty = tid >> 4;

    unsigned long long acc[8][4];                 // 8 rows x 4 fp32x2 col-pairs
    #pragma unroll
    for (int r = 0; r < 8; ++r)
        #pragma unroll
        for (int q = 0; q < 4; ++q) acc[r][q] = 0ull;

    for (int kc = 0; kc < Cc; kc += 32) {
        __syncthreads();
        #pragma unroll
        for (int i = 0; i < 4; ++i) {
            int f4 = tid + i * 256;               // 0..1023 float4 slots
            int c = f4 >> 5, n4 = f4 & 31;
            *(float4*)&Ws[c][n4*4] = *(const float4*)(WT + (kc + c)*Cc + n4*4);
            float4 pv = *(const float4*)(P + (kc + c)*Nn + n0 + n4*4);
            pv.x = fmaxf(pv.x, 0.f) + 0.01f * fminf(pv.x, 0.f);
            pv.y = fmaxf(pv.y, 0.f) + 0.01f * fminf(pv.y, 0.f);
            pv.z = fmaxf(pv.z, 0.f) + 0.01f * fminf(pv.z, 0.f);
            pv.w = fmaxf(pv.w, 0.f) + 0.01f * fminf(pv.w, 0.f);
            *(float4*)&Ps[c][n4*4] = pv;
        }
        __syncthreads();
        #pragma unroll
        for (int c = 0; c < 32; ++c) {
            float a[8];
            *(float4*)&a[0] = *(float4*)&Ws[c][ty*8];
            *(float4*)&a[4] = *(float4*)&Ws[c][ty*8 + 4];
            unsigned long long bp[4];
            *(ulonglong2*)&bp[0] = *(ulonglong2*)&Ps[c][tx*8];
            *(ulonglong2*)&bp[2] = *(ulonglong2*)&Ps[c][tx*8 + 4];
            #pragma unroll
            for (int r = 0; r < 8; ++r) {
                unsigned long long av;
                asm("mov.b64 %0, {%1, %1};" : "=l"(av) : "f"(a[r]));
                #pragma unroll
                for (int q = 0; q < 4; ++q)
                    asm("fma.rn.f32x2 %0, %1, %2, %0;"
                        : "+l"(acc[r][q]) : "l"(av), "l"(bp[q]));
            }
        }
    }

    union U { unsigned long long u; float2 f; };
    if (which == 0) {
        #pragma unroll
        for (int r = 0; r < 8; ++r) {
            int o = ty*8 + r;
            float v[8];
            #pragma unroll
            for (int q = 0; q < 4; ++q) { U t; t.u = acc[r][q]; v[2*q] = t.f.x; v[2*q+1] = t.f.y; }
            float* dst = g_center + (b*Cc + o)*Nn + n0 + tx*8;
            *(float4*)dst       = make_float4(v[0], v[1], v[2], v[3]);
            *(float4*)(dst + 4) = make_float4(v[4], v[5], v[6], v[7]);
        }
    } else {
        #pragma unroll
        for (int q = 0; q < 4; ++q) {
            float lo[8], hi[8];
            #pragma unroll
            for (int r = 0; r < 8; ++r) { U t; t.u = acc[r][q]; lo[r] = t.f.x; hi[r] = t.f.y; }
            int n = n0 + tx*8 + 2*q;
            float* d0 = g_gT + (b*Nn + n    )*Cc + ty*8;
            float* d1 = g_gT + (b*Nn + n + 1)*Cc + ty*8;
            *(float4*)d0       = make_float4(lo[0], lo[1], lo[2], lo[3]);
            *(float4*)(d0 + 4) = make_float4(lo[4], lo[5], lo[6], lo[7]);
            *(float4*)d1       = make_float4(hi[0], hi[1], hi[2], hi[3]);
            *(float4*)(d1 + 4) = make_float4(hi[4], hi[5], hi[6], hi[7]);
        }
    }
}

// ------------------------- combine: gather-sum + center + bias + residual --
__global__ __launch_bounds__(256) void combine_kernel(const float* __restrict__ points,
                                                      const float* __restrict__ bc,
                                                      const float* __restrict__ bg,
                                                      float* __restrict__ out) {
    __shared__ float sm[32][133];     // [n_local][o], pad 133 -> conflict-free transpose
    __shared__ int   sidx[32*20];
    int b  = blockIdx.y;
    int n0 = blockIdx.x * 32;
    int tid = threadIdx.x;

    for (int u = tid; u < 32*20; u += 256)
        sidx[u] = g_knn[(b*Nn + n0)*20 + u];
    __syncthreads();

    // phase A: neighbor gather-sum into sm[nl][o]
    int h = tid >> 7, o = tid & 127;
    for (int nl = h; nl < 32; nl += 2) {
        float acc = 0.f;
        #pragma unroll
        for (int k = 0; k < Kk; ++k) {
            int nb = sidx[nl*20 + k];          // global b*N+n index
            acc += g_gT[nb*Cc + o];
        }
        sm[nl][o] = acc;
    }
    __syncthreads();

    // phase B: transposed, coalesced write with center + bias + shortcut
    int w = tid >> 5, l = tid & 31;
    int n = n0 + l;
    #pragma unroll
    for (int oo = 0; oo < 16; ++oo) {
        int o2 = w + oo*8;
        int off = (b*Cc + o2)*Nn + n;
        float biasv = fmaf(20.f, bg[o2], bc[o2]);
        out[off] = (sm[l][o2] + g_center[off] + biasv) * (1.0f / 21.0f) + points[off];
    }
}

// ------------------------- launch -----------------------------------------
extern "C" void kernel_launch(void* const* d_in, const int* in_sizes, int n_in,
                              void* d_out, int out_size) {
    const float* xyz    = (const float*)d_in[0];
    const float* points = (const float*)d_in[1];
    const float* Wc     = (const float*)d_in[2];
    const float* bc     = (const float*)d_in[3];
    const float* Wg     = (const float*)d_in[4];
    const float* bg     = (const float*)d_in[5];
    float* out = (float*)d_out;

    int knn_smem = Nn*16 + KTHR*KSTGP*4 + KTHR*KSTGP*4;
    cudaFuncSetAttribute(knn_kernel, cudaFuncAttributeMaxDynamicSharedMemorySize, knn_smem);

    prep_kernel<<<128, 256>>>(Wc, Wg);
    knn_kernel<<<Bb*Nn/KTHR, KTHR, knn_smem>>>(xyz);
    gemm_kernel<<<dim3(Nn/128, Bb, 2), 256>>>(points);
    combine_kernel<<<dim3(Nn/32, Bb), 256>>>(points, bc, bg, out);
}

// round 8
// speedup vs baseline: 4.4567x; 1.2028x over previous
#include <cuda_runtime.h>

#define Bb 8
#define Nn 4096
#define Cc 128
#define Kk 20

// ------------------------- scratch (device globals, no allocs) -------------
__device__ int    g_knn[Bb*Nn*Kk];        // 20 neighbor indices per point (global b*N+n space)
__device__ float  g_wT[2*Cc*Cc];          // WcT then WgT, [c][o]
__device__ float  g_center[Bb*Cc*Nn];     // Wc @ leaky(p)         [b][o][n]
__device__ float  g_gT[Bb*Nn*Cc];         // (Wg @ leaky(p))^T     [b][n][o]

// ------------------------- prep: transpose weights -------------------------
__global__ __launch_bounds__(256) void prep_kernel(const float* __restrict__ Wc,
                                                   const float* __restrict__ Wg) {
    int t = blockIdx.x * 256 + threadIdx.x;   // 0 .. 2*128*128-1
    int which = t >> 14;                      // 0: Wc, 1: Wg
    int e = t & (Cc*Cc - 1);
    int o = e >> 7, c = e & 127;
    const float* W = which ? Wg : Wc;
    g_wT[which*Cc*Cc + c*Cc + o] = W[o*Cc + c];
}

// ------------------------- KNN (2 lanes per query) -------------------------
// Block: 256 threads = 128 queries x 2 lanes (lane pair = tid^1). Whole batch
// tile (64KB) in SMEM. Lane scans candidates of its parity (2048 each); every
// lane of a warp reads the SAME tile slot -> broadcast LDS. Sorted top-21
// (key,index) pairs in registers (self included; self key -|x|^2 is strict
// min). Staging: unconditional (d,j) store + cnt += (d<worst)  -- no
// predicated-store guard in the chain. Flush at any-lane cnt>=9 (depth 12,
// check every 4: capacity-exact), draining only reduce_max(cnt) slots.
// worst is shared across the lane pair (shfl-min): pruned d >= partner's
// current 21st >= global tau, so pruning is safe. Final merge: snapshot
// partner's sorted list via shfl, insert with early break; even lane writes.
#define KNN_INF  3.402823466e38f
#define KTHR 256
#define KSTG 12
#define KSTGP 13

__device__ __forceinline__ void pair_ins(float (&ds)[21], int (&ix)[21],
                                         float cd, int ci) {
    #pragma unroll
    for (int s = 0; s < 21; ++s) {
        bool t   = cd < ds[s];               // strict: earlier insert wins ties
        float mn = fminf(cd, ds[s]);
        float mx = fmaxf(cd, ds[s]);
        int  ni  = t ? ci : ix[s];
        ci       = t ? ix[s] : ci;
        ds[s] = mn; ix[s] = ni; cd = mx;
    }
}

__global__ __launch_bounds__(KTHR) void knn_kernel(const float* __restrict__ xyz) {
    extern __shared__ float sraw[];
    float4* tile = (float4*)sraw;                      // Nn float4 (64KB)
    float*  stgd = sraw + Nn*4;                        // KTHR*KSTGP floats
    int*    stgi = (int*)(stgd + KTHR*KSTGP);          // KTHR*KSTGP ints

    int tid  = threadIdx.x;
    int half = tid & 1;                                // candidate parity
    int qloc = tid >> 1;                               // 0..127
    int q0   = blockIdx.x * (KTHR/2);                  // first query of block
    int b    = q0 >> 12;
    const float* px = xyz + b * 3 * Nn;

    // pack this batch's xyz -> (x,y,z,|x|^2) tile
    for (int n = tid; n < Nn; n += KTHR) {
        float x = px[n], y = px[Nn + n], z = px[2*Nn + n];
        tile[n] = make_float4(x, y, z, fmaf(x, x, fmaf(y, y, z * z)));
    }
    __syncthreads();

    int selfn = (q0 & (Nn - 1)) + qloc;                // local index of own query
    float4 me = tile[selfn];
    float mx = -2.f * me.x, my = -2.f * me.y, mz = -2.f * me.z;

    float ds[21]; int ix[21];
    #pragma unroll
    for (int s = 0; s < 21; ++s) { ds[s] = KNN_INF; ix[s] = 0; }
    float worst = KNN_INF;
    int cnt = 0;
    float* sd = stgd + tid * KSTGP;
    int*   si = stgi + tid * KSTGP;

    #pragma unroll 1
    for (int i0 = 0; i0 < Nn/2; i0 += 4) {
        #pragma unroll
        for (int u = 0; u < 4; ++u) {
            int j = (i0 + u) * 2 + half;
            float4 c = tile[j];
            // rank key: |xj|^2 - 2*dot(xi,xj)  (same ordering as squared dist)
            float d = fmaf(mx, c.x, fmaf(my, c.y, fmaf(mz, c.z, c.w)));
            sd[cnt] = d; si[cnt] = j;                  // unconditional store
            cnt += (d < worst) ? 1 : 0;
        }
        if (__any_sync(0xffffffffu, cnt >= KSTG - 3)) {
            int um = __reduce_max_sync(0xffffffffu, cnt);
            #pragma unroll 1
            for (int u = 0; u < um; ++u) {
                float vd = sd[u]; int vi = si[u];
                pair_ins(ds, ix, (u < cnt) ? vd : KNN_INF, vi);
            }
            float wm = ds[20];
            float wp = __shfl_xor_sync(0xffffffffu, wm, 1);
            worst = fminf(wm, wp);
            cnt = 0;
        }
    }
    {   // final drain
        int um = __reduce_max_sync(0xffffffffu, cnt);
        #pragma unroll 1
        for (int u = 0; u < um; ++u) {
            float vd = sd[u]; int vi = si[u];
            pair_ins(ds, ix, (u < cnt) ? vd : KNN_INF, vi);
        }
    }

    // merge lane pair: snapshot partner's sorted list, then insert (early break)
    float od[21]; int oi[21];
    #pragma unroll
    for (int s = 0; s < 21; ++s) {
        od[s] = __shfl_xor_sync(0xffffffffu, ds[s], 1);
        oi[s] = __shfl_xor_sync(0xffffffffu, ix[s], 1);
    }
    #pragma unroll 1
    for (int s = 0; s < 21; ++s) {
        if (od[s] >= ds[20]) break;                    // od sorted: rest can't enter
        pair_ins(ds, ix, od[s], oi[s]);
    }

    if (half == 0) {
        int gq = q0 + qloc;
        int base = q0 & ~(Nn - 1);
        #pragma unroll
        for (int s = 0; s < 20; ++s) g_knn[gq*Kk + s] = base + ix[s + 1];  // drop self
    }
}

// ------------------------- fused GEMM: [Wc;Wg] @ leaky(P) ------------------
// grid (N/128, B, 2); z=0 -> center [b][o][n], z=1 -> gT transposed [b][n][o]
__global__ __launch_bounds__(256) void gemm_kernel(const float* __restrict__ points) {
    __shared__ __align__(16) float Ws[32][128];   // [c][o]
    __shared__ __align__(16) float Ps[32][128];   // [c][n]
    int b  = blockIdx.y;
    int n0 = blockIdx.x * 128;
    int which = blockIdx.z;
    const float* WT = g_wT + which * Cc * Cc;
    const float* P  = points + b * Cc * Nn;
    int tid = threadIdx.x;
    int tx = tid & 15, ty = tid >> 4;

    unsigned long long acc[8][4];                 // 8 rows x 4 fp32x2 col-pairs
    #pragma unroll
    for (int r = 0; r < 8; ++r)
        #pragma unroll
        for (int q = 0; q < 4; ++q) acc[r][q] = 0ull;

    for (int kc = 0; kc < Cc; kc += 32) {
        __syncthreads();
        #pragma unroll
        for (int i = 0; i < 4; ++i) {
            int f4 = tid + i * 256;               // 0..1023 float4 slots
            int c = f4 >> 5, n4 = f4 & 31;
            *(float4*)&Ws[c][n4*4] = *(const float4*)(WT + (kc + c)*Cc + n4*4);
            float4 pv = *(const float4*)(P + (kc + c)*Nn + n0 + n4*4);
            pv.x = fmaxf(pv.x, 0.f) + 0.01f * fminf(pv.x, 0.f);
            pv.y = fmaxf(pv.y, 0.f) + 0.01f * fminf(pv.y, 0.f);
            pv.z = fmaxf(pv.z, 0.f) + 0.01f * fminf(pv.z, 0.f);
            pv.w = fmaxf(pv.w, 0.f) + 0.01f * fminf(pv.w, 0.f);
            *(float4*)&Ps[c][n4*4] = pv;
        }
        __syncthreads();
        #pragma unroll
        for (int c = 0; c < 32; ++c) {
            float a[8];
            *(float4*)&a[0] = *(float4*)&Ws[c][ty*8];
            *(float4*)&a[4] = *(float4*)&Ws[c][ty*8 + 4];
            unsigned long long bp[4];
            *(ulonglong2*)&bp[0] = *(ulonglong2*)&Ps[c][tx*8];
            *(ulonglong2*)&bp[2] = *(ulonglong2*)&Ps[c][tx*8 + 4];
            #pragma unroll
            for (int r = 0; r < 8; ++r) {
                unsigned long long av;
                asm("mov.b64 %0, {%1, %1};" : "=l"(av) : "f"(a[r]));
                #pragma unroll
                for (int q = 0; q < 4; ++q)
                    asm("fma.rn.f32x2 %0, %1, %2, %0;"
                        : "+l"(acc[r][q]) : "l"(av), "l"(bp[q]));
            }
        }
    }

    union U { unsigned long long u; float2 f; };
    if (which == 0) {
        #pragma unroll
        for (int r = 0; r < 8; ++r) {
            int o = ty*8 + r;
            float v[8];
            #pragma unroll
            for (int q = 0; q < 4; ++q) { U t; t.u = acc[r][q]; v[2*q] = t.f.x; v[2*q+1] = t.f.y; }
            float* dst = g_center + (b*Cc + o)*Nn + n0 + tx*8;
            *(float4*)dst       = make_float4(v[0], v[1], v[2], v[3]);
            *(float4*)(dst + 4) = make_float4(v[4], v[5], v[6], v[7]);
        }
    } else {
        #pragma unroll
        for (int q = 0; q < 4; ++q) {
            float lo[8], hi[8];
            #pragma unroll
            for (int r = 0; r < 8; ++r) { U t; t.u = acc[r][q]; lo[r] = t.f.x; hi[r] = t.f.y; }
            int n = n0 + tx*8 + 2*q;
            float* d0 = g_gT + (b*Nn + n    )*Cc + ty*8;
            float* d1 = g_gT + (b*Nn + n + 1)*Cc + ty*8;
            *(float4*)d0       = make_float4(lo[0], lo[1], lo[2], lo[3]);
            *(float4*)(d0 + 4) = make_float4(lo[4], lo[5], lo[6], lo[7]);
            *(float4*)d1       = make_float4(hi[0], hi[1], hi[2], hi[3]);
            *(float4*)(d1 + 4) = make_float4(hi[4], hi[5], hi[6], hi[7]);
        }
    }
}

// ------------------------- combine: gather-sum + center + bias + residual --
__global__ __launch_bounds__(256) void combine_kernel(const float* __restrict__ points,
                                                      const float* __restrict__ bc,
                                                      const float* __restrict__ bg,
                                                      float* __restrict__ out) {
    __shared__ float sm[32][133];     // [n_local][o], pad 133 -> conflict-free transpose
    __shared__ int   sidx[32*20];
    int b  = blockIdx.y;
    int n0 = blockIdx.x * 32;
    int tid = threadIdx.x;

    for (int u = tid; u < 32*20; u += 256)
        sidx[u] = g_knn[(b*Nn + n0)*20 + u];
    __syncthreads();

    // phase A: neighbor gather-sum into sm[nl][o]
    int h = tid >> 7, o = tid & 127;
    for (int nl = h; nl < 32; nl += 2) {
        float acc = 0.f;
        #pragma unroll
        for (int k = 0; k < Kk; ++k) {
            int nb = sidx[nl*20 + k];          // global b*N+n index
            acc += g_gT[nb*Cc + o];
        }
        sm[nl][o] = acc;
    }
    __syncthreads();

    // phase B: transposed, coalesced write with center + bias + shortcut
    int w = tid >> 5, l = tid & 31;
    int n = n0 + l;
    #pragma unroll
    for (int oo = 0; oo < 16; ++oo) {
        int o2 = w + oo*8;
        int off = (b*Cc + o2)*Nn + n;
        float biasv = fmaf(20.f, bg[o2], bc[o2]);
        out[off] = (sm[l][o2] + g_center[off] + biasv) * (1.0f / 21.0f) + points[off];
    }
}

// ------------------------- launch -----------------------------------------
extern "C" void kernel_launch(void* const* d_in, const int* in_sizes, int n_in,
                              void* d_out, int out_size) {
    const float* xyz    = (const float*)d_in[0];
    const float* points = (const float*)d_in[1];
    const float* Wc     = (const float*)d_in[2];
    const float* bc     = (const float*)d_in[3];
    const float* Wg     = (const float*)d_in[4];
    const float* bg     = (const float*)d_in[5];
    float* out = (float*)d_out;

    int knn_smem = Nn*16 + KTHR*KSTGP*4 + KTHR*KSTGP*4;
    cudaFuncSetAttribute(knn_kernel, cudaFuncAttributeMaxDynamicSharedMemorySize, knn_smem);

    prep_kernel<<<128, 256>>>(Wc, Wg);
    knn_kernel<<<Bb*Nn/(KTHR/2), KTHR, knn_smem>>>(xyz);
    gemm_kernel<<<dim3(Nn/128, Bb, 2), 256>>>(points);
    combine_kernel<<<dim3(Nn/32, Bb), 256>>>(points, bc, bg, out);
}

// round 10
// speedup vs baseline: 5.2137x; 1.1699x over previous
#include <cuda_runtime.h>

#define Bb 8
#define Nn 4096
#define Cc 128
#define Kk 20

// ------------------------- scratch (device globals, no allocs) -------------
__device__ int    g_knn[Bb*Nn*Kk];        // 20 neighbor indices per point (global b*N+n space)
__device__ float  g_wT[2*Cc*Cc];          // WcT then WgT, [c][o]
__device__ float  g_center[Bb*Cc*Nn];     // Wc @ leaky(p)         [b][o][n]
__device__ float  g_gT[Bb*Nn*Cc];         // (Wg @ leaky(p))^T     [b][n][o]

// ------------------------- prep: transpose weights -------------------------
__global__ __launch_bounds__(256) void prep_kernel(const float* __restrict__ Wc,
                                                   const float* __restrict__ Wg) {
    int t = blockIdx.x * 256 + threadIdx.x;   // 0 .. 2*128*128-1
    int which = t >> 14;                      // 0: Wc, 1: Wg
    int e = t & (Cc*Cc - 1);
    int o = e >> 7, c = e & 127;
    const float* W = which ? Wg : Wc;
    g_wT[which*Cc*Cc + c*Cc + o] = W[o*Cc + c];
}

// ------------------------- KNN (2 lanes/query, balanced grid) --------------
// Grid: 37 blocks per batch x 8 = 296 blocks (2/SM on every SM -> no skew).
// Block: 256 threads = 128 query slots x 2 lanes; QPBLK=111 queries used
// (last block 100); idle slots run with worst=-INF (never stage/write).
// NOTE: every warp collective (any_sync / reduce_max / shfl) is executed by
// ALL lanes on uniform control flow; activity only gates the SELECT of the
// result (the R9 deadlock was a full-mask shfl under divergence).
// Whole batch tile (64KB) in SMEM. Lane scans its parity half (2048 cands).
// Staging: (d,j) packed in one u64, STS.64; depth 20, trigger cnt>=16,
// vote every 4 (max cnt 19 < 20: capacity-exact). Store addresses via
// qualify-flag prefix (no serial cnt chain). Flush drains reduce_max(cnt)
// slots through the 21-deep FMNMX/SEL network (invalid -> +INF no-op).
// worst shared across the lane pair via shfl-min (safe: pruned d >=
// partner's 21st >= query tau). Final pair merge via register snapshot +
// early-break insert; even lane writes ix[1..20] (slot 0 provably self).
#define KNN_INF  3.402823466e38f
#define KTHR 256
#define KSTG 20
#define QPBLK 111
#define BPB 37

__device__ __forceinline__ void pair_ins(float (&ds)[21], int (&ix)[21],
                                         float cd, int ci) {
    #pragma unroll
    for (int s = 0; s < 21; ++s) {
        bool t   = cd < ds[s];               // strict: earlier insert wins ties
        float mn = fminf(cd, ds[s]);
        float mx = fmaxf(cd, ds[s]);
        int  ni  = t ? ci : ix[s];
        ci       = t ? ix[s] : ci;
        ds[s] = mn; ix[s] = ni; cd = mx;
    }
}

__device__ __forceinline__ unsigned long long dj_pack(float d, int j) {
    unsigned long long r;
    asm("mov.b64 %0, {%1, %2};" : "=l"(r) : "r"(j), "f"(d));
    return r;
}
__device__ __forceinline__ void dj_unpack(unsigned long long v, float& d, int& j) {
    asm("mov.b64 {%0, %1}, %2;" : "=r"(j), "=f"(d) : "l"(v));
}

__global__ __launch_bounds__(KTHR, 2) void knn_kernel(const float* __restrict__ xyz) {
    extern __shared__ float sraw[];
    float4* tile = (float4*)sraw;                              // Nn float4 (64KB)
    unsigned long long* stg = (unsigned long long*)(sraw + Nn*4);  // KTHR*(KSTG+1) u64

    int tid  = threadIdx.x;
    int half = tid & 1;                                // candidate parity
    int qloc = tid >> 1;                               // 0..127 (slots; QPBLK used)
    int bib  = blockIdx.x % BPB;                       // block-in-batch 0..36
    int b    = blockIdx.x / BPB;
    int qstart = bib * QPBLK;
    int qcount = min(QPBLK, Nn - qstart);
    const float* px = xyz + b * 3 * Nn;

    // pack this batch's xyz -> (x,y,z,|x|^2) tile
    for (int n = tid; n < Nn; n += KTHR) {
        float x = px[n], y = px[Nn + n], z = px[2*Nn + n];
        tile[n] = make_float4(x, y, z, fmaf(x, x, fmaf(y, y, z * z)));
    }
    __syncthreads();

    bool active = qloc < qcount;
    int selfn = qstart + (active ? qloc : 0);
    float4 me = tile[selfn];
    float mx = -2.f * me.x, my = -2.f * me.y, mz = -2.f * me.z;

    float ds[21]; int ix[21];
    #pragma unroll
    for (int s = 0; s < 21; ++s) { ds[s] = KNN_INF; ix[s] = 0; }
    float worst = active ? KNN_INF : -KNN_INF;         // idle: never qualifies
    int cnt = 0;
    unsigned long long* st = stg + tid * (KSTG + 1);

    #pragma unroll 1
    for (int i0 = 0; i0 < Nn/2; i0 += 4) {
        // 4 candidates, independent flags, prefix-addressed stores
        float dd[4]; int jj[4]; bool qf[4];
        #pragma unroll
        for (int u = 0; u < 4; ++u) {
            jj[u] = (i0 + u) * 2 + half;
            float4 c = tile[jj[u]];
            dd[u] = fmaf(mx, c.x, fmaf(my, c.y, fmaf(mz, c.z, c.w)));
            qf[u] = dd[u] < worst;
        }
        int c0 = cnt;
        int c1 = c0 + qf[0];
        int c2 = c1 + qf[1];
        int c3 = c2 + qf[2];
        if (qf[0]) st[c0] = dj_pack(dd[0], jj[0]);
        if (qf[1]) st[c1] = dj_pack(dd[1], jj[1]);
        if (qf[2]) st[c2] = dj_pack(dd[2], jj[2]);
        if (qf[3]) st[c3] = dj_pack(dd[3], jj[3]);
        cnt = c3 + qf[3];

        if (__any_sync(0xffffffffu, cnt >= KSTG - 4)) {
            int um = __reduce_max_sync(0xffffffffu, cnt);
            #pragma unroll 1
            for (int u = 0; u < um; ++u) {
                float vd; int vi;
                dj_unpack(st[u], vd, vi);
                pair_ins(ds, ix, (u < cnt) ? vd : KNN_INF, vi);
            }
            // collectives unconditional; activity gates only the select
            float wm = ds[20];
            float wp = __shfl_xor_sync(0xffffffffu, wm, 1);
            worst = active ? fminf(wm, wp) : -KNN_INF;
            cnt = 0;
        }
    }
    {   // final drain
        int um = __reduce_max_sync(0xffffffffu, cnt);
        #pragma unroll 1
        for (int u = 0; u < um; ++u) {
            float vd; int vi;
            dj_unpack(st[u], vd, vi);
            pair_ins(ds, ix, (u < cnt) ? vd : KNN_INF, vi);
        }
    }

    // merge lane pair: snapshot partner's sorted list, insert w/ early break
    float od[21]; int oi[21];
    #pragma unroll
    for (int s = 0; s < 21; ++s) {
        od[s] = __shfl_xor_sync(0xffffffffu, ds[s], 1);
        oi[s] = __shfl_xor_sync(0xffffffffu, ix[s], 1);
    }
    #pragma unroll 1
    for (int s = 0; s < 21; ++s) {
        if (od[s] >= ds[20]) break;                    // od sorted: rest can't enter
        pair_ins(ds, ix, od[s], oi[s]);
    }

    if (half == 0 && active) {
        int gq = b * Nn + qstart + qloc;
        int base = b * Nn;
        #pragma unroll
        for (int s = 0; s < 20; ++s) g_knn[gq*Kk + s] = base + ix[s + 1];  // drop self
    }
}

// ------------------------- fused GEMM: [Wc;Wg] @ leaky(P) ------------------
// grid (N/128, B, 2); z=0 -> center [b][o][n], z=1 -> gT transposed [b][n][o]
__global__ __launch_bounds__(256) void gemm_kernel(const float* __restrict__ points) {
    __shared__ __align__(16) float Ws[32][128];   // [c][o]
    __shared__ __align__(16) float Ps[32][128];   // [c][n]
    int b  = blockIdx.y;
    int n0 = blockIdx.x * 128;
    int which = blockIdx.z;
    const float* WT = g_wT + which * Cc * Cc;
    const float* P  = points + b * Cc * Nn;
    int tid = threadIdx.x;
    int tx = tid & 15, ty = tid >> 4;

    unsigned long long acc[8][4];                 // 8 rows x 4 fp32x2 col-pairs
    #pragma unroll
    for (int r = 0; r < 8; ++r)
        #pragma unroll
        for (int q = 0; q < 4; ++q) acc[r][q] = 0ull;

    for (int kc = 0; kc < Cc; kc += 32) {
        __syncthreads();
        #pragma unroll
        for (int i = 0; i < 4; ++i) {
            int f4 = tid + i * 256;               // 0..1023 float4 slots
            int c = f4 >> 5, n4 = f4 & 31;
            *(float4*)&Ws[c][n4*4] = *(const float4*)(WT + (kc + c)*Cc + n4*4);
            float4 pv = *(const float4*)(P + (kc + c)*Nn + n0 + n4*4);
            pv.x = fmaxf(pv.x, 0.f) + 0.01f * fminf(pv.x, 0.f);
            pv.y = fmaxf(pv.y, 0.f) + 0.01f * fminf(pv.y, 0.f);
            pv.z = fmaxf(pv.z, 0.f) + 0.01f * fminf(pv.z, 0.f);
            pv.w = fmaxf(pv.w, 0.f) + 0.01f * fminf(pv.w, 0.f);
            *(float4*)&Ps[c][n4*4] = pv;
        }
        __syncthreads();
        #pragma unroll
        for (int c = 0; c < 32; ++c) {
            float a[8];
            *(float4*)&a[0] = *(float4*)&Ws[c][ty*8];
            *(float4*)&a[4] = *(float4*)&Ws[c][ty*8 + 4];
            unsigned long long bp[4];
            *(ulonglong2*)&bp[0] = *(ulonglong2*)&Ps[c][tx*8];
            *(ulonglong2*)&bp[2] = *(ulonglong2*)&Ps[c][tx*8 + 4];
            #pragma unroll
            for (int r = 0; r < 8; ++r) {
                unsigned long long av;
                asm("mov.b64 %0, {%1, %1};" : "=l"(av) : "f"(a[r]));
                #pragma unroll
                for (int q = 0; q < 4; ++q)
                    asm("fma.rn.f32x2 %0, %1, %2, %0;"
                        : "+l"(acc[r][q]) : "l"(av), "l"(bp[q]));
            }
        }
    }

    union U { unsigned long long u; float2 f; };
    if (which == 0) {
        #pragma unroll
        for (int r = 0; r < 8; ++r) {
            int o = ty*8 + r;
            float v[8];
            #pragma unroll
            for (int q = 0; q < 4; ++q) { U t; t.u = acc[r][q]; v[2*q] = t.f.x; v[2*q+1] = t.f.y; }
            float* dst = g_center + (b*Cc + o)*Nn + n0 + tx*8;
            *(float4*)dst       = make_float4(v[0], v[1], v[2], v[3]);
            *(float4*)(dst + 4) = make_float4(v[4], v[5], v[6], v[7]);
        }
    } else {
        #pragma unroll
        for (int q = 0; q < 4; ++q) {
            float lo[8], hi[8];
            #pragma unroll
            for (int r = 0; r < 8; ++r) { U t; t.u = acc[r][q]; lo[r] = t.f.x; hi[r] = t.f.y; }
            int n = n0 + tx*8 + 2*q;
            float* d0 = g_gT + (b*Nn + n    )*Cc + ty*8;
            float* d1 = g_gT + (b*Nn + n + 1)*Cc + ty*8;
            *(float4*)d0       = make_float4(lo[0], lo[1], lo[2], lo[3]);
            *(float4*)(d0 + 4) = make_float4(lo[4], lo[5], lo[6], lo[7]);
            *(float4*)d1       = make_float4(hi[0], hi[1], hi[2], hi[3]);
            *(float4*)(d1 + 4) = make_float4(hi[4], hi[5], hi[6], hi[7]);
        }
    }
}

// ------------------------- combine: gather-sum + center + bias + residual --
__global__ __launch_bounds__(256) void combine_kernel(const float* __restrict__ points,
                                                      const float* __restrict__ bc,
                                                      const float* __restrict__ bg,
                                                      float* __restrict__ out) {
    __shared__ float sm[32][133];     // [n_local][o], pad 133 -> conflict-free transpose
    __shared__ int   sidx[32*20];
    int b  = blockIdx.y;
    int n0 = blockIdx.x * 32;
    int tid = threadIdx.x;

    for (int u = tid; u < 32*20; u += 256)
        sidx[u] = g_knn[(b*Nn + n0)*20 + u];
    __syncthreads();

    // phase A: neighbor gather-sum into sm[nl][o]
    int h = tid >> 7, o = tid & 127;
    for (int nl = h; nl < 32; nl += 2) {
        float acc = 0.f;
        #pragma unroll
        for (int k = 0; k < Kk; ++k) {
            int nb = sidx[nl*20 + k];          // global b*N+n index
            acc += g_gT[nb*Cc + o];
        }
        sm[nl][o] = acc;
    }
    __syncthreads();

    // phase B: transposed, coalesced write with center + bias + shortcut
    int w = tid >> 5, l = tid & 31;
    int n = n0 + l;
    #pragma unroll
    for (int oo = 0; oo < 16; ++oo) {
        int o2 = w + oo*8;
        int off = (b*Cc + o2)*Nn + n;
        float biasv = fmaf(20.f, bg[o2], bc[o2]);
        out[off] = (sm[l][o2] + g_center[off] + biasv) * (1.0f / 21.0f) + points[off];
    }
}

// ------------------------- launch -----------------------------------------
extern "C" void kernel_launch(void* const* d_in, const int* in_sizes, int n_in,
                              void* d_out, int out_size) {
    const float* xyz    = (const float*)d_in[0];
    const float* points = (const float*)d_in[1];
    const float* Wc     = (const float*)d_in[2];
    const float* bc     = (const float*)d_in[3];
    const float* Wg     = (const float*)d_in[4];
    const float* bg     = (const float*)d_in[5];
    float* out = (float*)d_out;

    int knn_smem = Nn*16 + KTHR*(KSTG+1)*8;
    cudaFuncSetAttribute(knn_kernel, cudaFuncAttributeMaxDynamicSharedMemorySize, knn_smem);

    prep_kernel<<<128, 256>>>(Wc, Wg);
    knn_kernel<<<Bb*BPB, KTHR, knn_smem>>>(xyz);
    gemm_kernel<<<dim3(Nn/128, Bb, 2), 256>>>(points);
    combine_kernel<<<dim3(Nn/32, Bb), 256>>>(points, bc, bg, out);
}

// round 11
// speedup vs baseline: 5.6695x; 1.0874x over previous
#include <cuda_runtime.h>
#include <cuda_fp16.h>

#define Bb 8
#define Nn 4096
#define Cc 128
#define Kk 20

// ------------------------- scratch (device globals, no allocs) -------------
__device__ int    g_knn[Bb*Nn*Kk];        // 20 neighbor indices per point (global b*N+n space)
__device__ float  g_wT[2*Cc*Cc];          // WcT then WgT, [c][o]
__device__ float  g_center[Bb*Cc*Nn];     // Wc @ leaky(p)         [b][o][n]
__device__ __half g_hT[Bb*Nn*Cc];         // (Wg @ leaky(p))^T in fp16  [b][n][o]

// ------------------------- prep: transpose weights -------------------------
__global__ __launch_bounds__(256) void prep_kernel(const float* __restrict__ Wc,
                                                   const float* __restrict__ Wg) {
    int t = blockIdx.x * 256 + threadIdx.x;   // 0 .. 2*128*128-1
    int which = t >> 14;                      // 0: Wc, 1: Wg
    int e = t & (Cc*Cc - 1);
    int o = e >> 7, c = e & 127;
    const float* W = which ? Wg : Wc;
    g_wT[which*Cc*Cc + c*Cc + o] = W[o*Cc + c];
}

// ------------------------- KNN (2 lanes/query, balanced grid) --------------
// Grid: 37 blocks per batch x 8 = 296 blocks (2/SM on every SM -> no skew).
// Block: 256 threads = 128 query slots x 2 lanes; QPBLK=111 queries used
// (last block 100); idle slots run with worst=-INF (never stage/write).
// All warp collectives execute on uniform control flow for all lanes;
// activity gates only result selects. Whole batch tile (64KB) in SMEM; lane
// scans its parity half. Staging: (d,j) packed u64, STS.64; depth 20,
// trigger cnt>=12, vote every 8 candidates (12+8=20: capacity-exact).
// Qualify-flag prefix store addressing (no serial cnt chain). Flush drains
// reduce_max(cnt) slots through the 21-deep FMNMX/SEL network (invalid ->
// +INF no-op). worst shared across the lane pair via shfl-min. Final pair
// merge via register snapshot + early-break insert; even lane writes
// ix[1..20] (slot 0 provably self).
#define KNN_INF  3.402823466e38f
#define KTHR 256
#define KSTG 20
#define QPBLK 111
#define BPB 37

__device__ __forceinline__ void pair_ins(float (&ds)[21], int (&ix)[21],
                                         float cd, int ci) {
    #pragma unroll
    for (int s = 0; s < 21; ++s) {
        bool t   = cd < ds[s];               // strict: earlier insert wins ties
        float mn = fminf(cd, ds[s]);
        float mx = fmaxf(cd, ds[s]);
        int  ni  = t ? ci : ix[s];
        ci       = t ? ix[s] : ci;
        ds[s] = mn; ix[s] = ni; cd = mx;
    }
}

__device__ __forceinline__ unsigned long long dj_pack(float d, int j) {
    unsigned long long r;
    asm("mov.b64 %0, {%1, %2};" : "=l"(r) : "r"(j), "f"(d));
    return r;
}
__device__ __forceinline__ void dj_unpack(unsigned long long v, float& d, int& j) {
    asm("mov.b64 {%0, %1}, %2;" : "=r"(j), "=f"(d) : "l"(v));
}

__global__ __launch_bounds__(KTHR, 2) void knn_kernel(const float* __restrict__ xyz) {
    extern __shared__ float sraw[];
    float4* tile = (float4*)sraw;                              // Nn float4 (64KB)
    unsigned long long* stg = (unsigned long long*)(sraw + Nn*4);  // KTHR*(KSTG+1) u64

    int tid  = threadIdx.x;
    int half = tid & 1;                                // candidate parity
    int qloc = tid >> 1;                               // 0..127 (slots; QPBLK used)
    int bib  = blockIdx.x % BPB;                       // block-in-batch 0..36
    int b    = blockIdx.x / BPB;
    int qstart = bib * QPBLK;
    int qcount = min(QPBLK, Nn - qstart);
    const float* px = xyz + b * 3 * Nn;

    // pack this batch's xyz -> (x,y,z,|x|^2) tile
    for (int n = tid; n < Nn; n += KTHR) {
        float x = px[n], y = px[Nn + n], z = px[2*Nn + n];
        tile[n] = make_float4(x, y, z, fmaf(x, x, fmaf(y, y, z * z)));
    }
    __syncthreads();

    bool active = qloc < qcount;
    int selfn = qstart + (active ? qloc : 0);
    float4 me = tile[selfn];
    float mx = -2.f * me.x, my = -2.f * me.y, mz = -2.f * me.z;

    float ds[21]; int ix[21];
    #pragma unroll
    for (int s = 0; s < 21; ++s) { ds[s] = KNN_INF; ix[s] = 0; }
    float worst = active ? KNN_INF : -KNN_INF;         // idle: never qualifies
    int cnt = 0;
    unsigned long long* st = stg + tid * (KSTG + 1);

    #pragma unroll 1
    for (int i0 = 0; i0 < Nn/2; i0 += 8) {
        // 8 candidates, independent flags, prefix-addressed stores
        float dd[8]; int jj[8]; bool qf[8];
        #pragma unroll
        for (int u = 0; u < 8; ++u) {
            jj[u] = (i0 + u) * 2 + half;
            float4 c = tile[jj[u]];
            dd[u] = fmaf(mx, c.x, fmaf(my, c.y, fmaf(mz, c.z, c.w)));
            qf[u] = dd[u] < worst;
        }
        int cc = cnt;
        #pragma unroll
        for (int u = 0; u < 8; ++u) {
            if (qf[u]) st[cc] = dj_pack(dd[u], jj[u]);
            cc += qf[u];
        }
        cnt = cc;

        if (__any_sync(0xffffffffu, cnt >= KSTG - 8)) {
            int um = __reduce_max_sync(0xffffffffu, cnt);
            #pragma unroll 1
            for (int u = 0; u < um; ++u) {
                float vd; int vi;
                dj_unpack(st[u], vd, vi);
                pair_ins(ds, ix, (u < cnt) ? vd : KNN_INF, vi);
            }
            // collectives unconditional; activity gates only the select
            float wm = ds[20];
            float wp = __shfl_xor_sync(0xffffffffu, wm, 1);
            worst = active ? fminf(wm, wp) : -KNN_INF;
            cnt = 0;
        }
    }
    {   // final drain
        int um = __reduce_max_sync(0xffffffffu, cnt);
        #pragma unroll 1
        for (int u = 0; u < um; ++u) {
            float vd; int vi;
            dj_unpack(st[u], vd, vi);
            pair_ins(ds, ix, (u < cnt) ? vd : KNN_INF, vi);
        }
    }

    // merge lane pair: snapshot partner's sorted list, insert w/ early break
    float od[21]; int oi[21];
    #pragma unroll
    for (int s = 0; s < 21; ++s) {
        od[s] = __shfl_xor_sync(0xffffffffu, ds[s], 1);
        oi[s] = __shfl_xor_sync(0xffffffffu, ix[s], 1);
    }
    #pragma unroll 1
    for (int s = 0; s < 21; ++s) {
        if (od[s] >= ds[20]) break;                    // od sorted: rest can't enter
        pair_ins(ds, ix, od[s], oi[s]);
    }

    if (half == 0 && active) {
        int gq = b * Nn + qstart + qloc;
        int base = b * Nn;
        #pragma unroll
        for (int s = 0; s < 20; ++s) g_knn[gq*Kk + s] = base + ix[s + 1];  // drop self
    }
}

// ------------------------- fused GEMM: [Wc;Wg] @ leaky(P) ------------------
// grid (N/128, B, 2); z=0 -> center [b][o][n] f32; z=1 -> g_hT [b][n][o] fp16
__global__ __launch_bounds__(256) void gemm_kernel(const float* __restrict__ points) {
    __shared__ __align__(16) float Ws[32][128];   // [c][o]
    __shared__ __align__(16) float Ps[32][128];   // [c][n]
    int b  = blockIdx.y;
    int n0 = blockIdx.x * 128;
    int which = blockIdx.z;
    const float* WT = g_wT + which * Cc * Cc;
    const float* P  = points + b * Cc * Nn;
    int tid = threadIdx.x;
    int tx = tid & 15, ty = tid >> 4;

    unsigned long long acc[8][4];                 // 8 rows x 4 fp32x2 col-pairs
    #pragma unroll
    for (int r = 0; r < 8; ++r)
        #pragma unroll
        for (int q = 0; q < 4; ++q) acc[r][q] = 0ull;

    for (int kc = 0; kc < Cc; kc += 32) {
        __syncthreads();
        #pragma unroll
        for (int i = 0; i < 4; ++i) {
            int f4 = tid + i * 256;               // 0..1023 float4 slots
            int c = f4 >> 5, n4 = f4 & 31;
            *(float4*)&Ws[c][n4*4] = *(const float4*)(WT + (kc + c)*Cc + n4*4);
            float4 pv = *(const float4*)(P + (kc + c)*Nn + n0 + n4*4);
            pv.x = fmaxf(pv.x, 0.f) + 0.01f * fminf(pv.x, 0.f);
            pv.y = fmaxf(pv.y, 0.f) + 0.01f * fminf(pv.y, 0.f);
            pv.z = fmaxf(pv.z, 0.f) + 0.01f * fminf(pv.z, 0.f);
            pv.w = fmaxf(pv.w, 0.f) + 0.01f * fminf(pv.w, 0.f);
            *(float4*)&Ps[c][n4*4] = pv;
        }
        __syncthreads();
        #pragma unroll
        for (int c = 0; c < 32; ++c) {
            float a[8];
            *(float4*)&a[0] = *(float4*)&Ws[c][ty*8];
            *(float4*)&a[4] = *(float4*)&Ws[c][ty*8 + 4];
            unsigned long long bp[4];
            *(ulonglong2*)&bp[0] = *(ulonglong2*)&Ps[c][tx*8];
            *(ulonglong2*)&bp[2] = *(ulonglong2*)&Ps[c][tx*8 + 4];
            #pragma unroll
            for (int r = 0; r < 8; ++r) {
                unsigned long long av;
                asm("mov.b64 %0, {%1, %1};" : "=l"(av) : "f"(a[r]));
                #pragma unroll
                for (int q = 0; q < 4; ++q)
                    asm("fma.rn.f32x2 %0, %1, %2, %0;"
                        : "+l"(acc[r][q]) : "l"(av), "l"(bp[q]));
            }
        }
    }

    union U { unsigned long long u; float2 f; };
    if (which == 0) {
        #pragma unroll
        for (int r = 0; r < 8; ++r) {
            int o = ty*8 + r;
            float v[8];
            #pragma unroll
            for (int q = 0; q < 4; ++q) { U t; t.u = acc[r][q]; v[2*q] = t.f.x; v[2*q+1] = t.f.y; }
            float* dst = g_center + (b*Cc + o)*Nn + n0 + tx*8;
            *(float4*)dst       = make_float4(v[0], v[1], v[2], v[3]);
            *(float4*)(dst + 4) = make_float4(v[4], v[5], v[6], v[7]);
        }
    } else {
        #pragma unroll
        for (int q = 0; q < 4; ++q) {
            float lo[8], hi[8];
            #pragma unroll
            for (int r = 0; r < 8; ++r) { U t; t.u = acc[r][q]; lo[r] = t.f.x; hi[r] = t.f.y; }
            int n = n0 + tx*8 + 2*q;
            union PK { __half2 h2[4]; uint4 u; } p0, p1;
            #pragma unroll
            for (int s = 0; s < 4; ++s) {
                p0.h2[s] = __floats2half2_rn(lo[2*s], lo[2*s+1]);
                p1.h2[s] = __floats2half2_rn(hi[2*s], hi[2*s+1]);
            }
            __half* d0 = g_hT + ((size_t)(b*Nn + n    ))*Cc + ty*8;
            __half* d1 = g_hT + ((size_t)(b*Nn + n + 1))*Cc + ty*8;
            *(uint4*)d0 = p0.u;
            *(uint4*)d1 = p1.u;
        }
    }
}

// ------------------------- combine: gather-sum + center + bias + residual --
__global__ __launch_bounds__(256) void combine_kernel(const float* __restrict__ points,
                                                      const float* __restrict__ bc,
                                                      const float* __restrict__ bg,
                                                      float* __restrict__ out) {
    __shared__ float sm[32][133];     // [n_local][o], pad 133 -> conflict-free transpose
    __shared__ int   sidx[32*20];
    int b  = blockIdx.y;
    int n0 = blockIdx.x * 32;
    int tid = threadIdx.x;

    for (int u = tid; u < 32*20; u += 256)
        sidx[u] = g_knn[(b*Nn + n0)*20 + u];
    __syncthreads();

    // phase A: neighbor gather-sum (fp16 payload, fp32 accumulate)
    int h = tid >> 6, o2 = tid & 63;          // 4 rows in flight, 64 half2-lanes
    for (int nl = h; nl < 32; nl += 4) {
        float ax = 0.f, ay = 0.f;
        #pragma unroll
        for (int k = 0; k < Kk; ++k) {
            int nb = sidx[nl*20 + k];          // global b*N+n index
            __half2 v = *(const __half2*)(g_hT + (size_t)nb*Cc + o2*2);
            float2 f = __half22float2(v);
            ax += f.x; ay += f.y;
        }
        sm[nl][o2*2]     = ax;
        sm[nl][o2*2 + 1] = ay;
    }
    __syncthreads();

    // phase B: transposed, coalesced write with center + bias + shortcut
    int w = tid >> 5, l = tid & 31;
    int n = n0 + l;
    #pragma unroll
    for (int oo = 0; oo < 16; ++oo) {
        int o2b = w + oo*8;
        int off = (b*Cc + o2b)*Nn + n;
        float biasv = fmaf(20.f, bg[o2b], bc[o2b]);
        out[off] = (sm[l][o2b] + g_center[off] + biasv) * (1.0f / 21.0f) + points[off];
    }
}

// ------------------------- launch -----------------------------------------
extern "C" void kernel_launch(void* const* d_in, const int* in_sizes, int n_in,
                              void* d_out, int out_size) {
    const float* xyz    = (const float*)d_in[0];
    const float* points = (const float*)d_in[1];
    const float* Wc     = (const float*)d_in[2];
    const float* bc     = (const float*)d_in[3];
    const float* Wg     = (const float*)d_in[4];
    const float* bg     = (const float*)d_in[5];
    float* out = (float*)d_out;

    int knn_smem = Nn*16 + KTHR*(KSTG+1)*8;
    cudaFuncSetAttribute(knn_kernel, cudaFuncAttributeMaxDynamicSharedMemorySize, knn_smem);

    prep_kernel<<<128, 256>>>(Wc, Wg);
    knn_kernel<<<Bb*BPB, KTHR, knn_smem>>>(xyz);
    gemm_kernel<<<dim3(Nn/128, Bb, 2), 256>>>(points);
    combine_kernel<<<dim3(Nn/32, Bb), 256>>>(points, bc, bg, out);
}